// round 14
// baseline (speedup 1.0000x reference)
#include <cuda_runtime.h>
#include <cuda_bf16.h>

typedef unsigned int       u32;
typedef unsigned long long u64;

#define BSZ      64
#define ENC_IN   64
#define ENC_HID  256
#define NNODES   2048
#define GHD      128
#define JTOT     (NNODES * GHD)      // 262144
#define LN_EPS   1e-5f

#define N_ENC_BLK NNODES             // 2048 (one node per enc block)
#define GCN_TILES 35                 // 35 x 60 outputs >= 2048
#define N_GCN_BLK (GCN_TILES * BSZ)  // 2240

// ---------------- scratch (device globals: allocation-guard safe) ----------
__device__ float g_h1[BSZ * ENC_HID];                  // [m][k] h1 rows
__device__ float g_buf0[(size_t)BSZ * NNODES * GHD];   // enc output
// A (=h1) bf16 hi/lo smem-image, row stride 528B (132 u32), 64 rows
__device__ __align__(16) u32 g_AH[64 * 132];
__device__ __align__(16) u32 g_AL[64 * 132];
// Wg1 transposed [n][k] bf16 hi/lo image, row stride 136 halfs (= 68 u32)
__device__ __align__(16) u32 g_BH[GHD * 68];
__device__ __align__(16) u32 g_BL[GHD * 68];
// layer-2 collapse: w2o = Wg2 @ Wout; gw = g2*w2o; K = {sum gw, sum b2*w2o}
__device__ float g_gw[GHD];
__device__ float g_K[2];
// per-node completion flags for producer/consumer safety
__device__ int g_flag[NNODES];

extern __shared__ __align__(1024) char dynsm[];

// ---------------- helpers ---------------------------------------------------
__device__ __forceinline__ u32 smem_u32(const void* p) {
    u32 a;
    asm("{ .reg .u64 t; cvta.to.shared.u64 t, %1; cvt.u32.u64 %0, t; }"
        : "=r"(a) : "l"(p));
    return a;
}
__device__ __forceinline__ void ldsm4(u32* r, u32 a) {
    asm volatile("ldmatrix.sync.aligned.m8n8.x4.shared.b16 {%0,%1,%2,%3}, [%4];"
                 : "=r"(r[0]), "=r"(r[1]), "=r"(r[2]), "=r"(r[3]) : "r"(a));
}
__device__ __forceinline__ void ldsm4t(u32* r, u32 a) {
    asm volatile("ldmatrix.sync.aligned.m8n8.x4.trans.shared.b16 {%0,%1,%2,%3}, [%4];"
                 : "=r"(r[0]), "=r"(r[1]), "=r"(r[2]), "=r"(r[3]) : "r"(a));
}
__device__ __forceinline__ void mma16816(float* c, const u32* a, u32 b0, u32 b1) {
    asm volatile(
        "mma.sync.aligned.m16n8k16.row.col.f32.bf16.bf16.f32 "
        "{%0,%1,%2,%3}, {%4,%5,%6,%7}, {%8,%9}, {%0,%1,%2,%3};"
        : "+f"(c[0]), "+f"(c[1]), "+f"(c[2]), "+f"(c[3])
        : "r"(a[0]), "r"(a[1]), "r"(a[2]), "r"(a[3]), "r"(b0), "r"(b1));
}
__device__ __forceinline__ void split2(float a, float b, u32& hi, u32& lo) {
    __nv_bfloat162 h = __floats2bfloat162_rn(a, b);
    float ha = __bfloat162float(h.x), hb = __bfloat162float(h.y);
    __nv_bfloat162 l = __floats2bfloat162_rn(a - ha, b - hb);
    hi = *reinterpret_cast<u32*>(&h);
    lo = *reinterpret_cast<u32*>(&l);
}

// ===========================================================================
// K_INIT (66 blocks): 0..63 flag reset + h1 + A-image row; 64 Wg1 image;
// 65 layer-2 collapse vectors.
// ===========================================================================
__global__ void k_init(const float* __restrict__ x,
                       const float* __restrict__ W1,
                       const float* __restrict__ b1,
                       const float* __restrict__ Wg1,
                       const float* __restrict__ Wg2,
                       const float* __restrict__ Wout,
                       const float* __restrict__ g2,
                       const float* __restrict__ b2ln) {
    const int bx = blockIdx.x;
    const int j  = threadIdx.x;
    if (bx < 64) {
        if (j < 32) g_flag[bx * 32 + j] = 0;
        __shared__ float sx[ENC_IN];
        __shared__ float sh[ENC_HID];
        if (j < ENC_IN) sx[j] = x[bx * ENC_IN + j];
        __syncthreads();
        float acc = b1[j];
#pragma unroll
        for (int k = 0; k < ENC_IN; k++)
            acc = fmaf(sx[k], W1[k * ENC_HID + j], acc);
        float h = fmaxf(acc, 0.0f);
        g_h1[bx * ENC_HID + j] = h;
        sh[j] = h;
        __syncthreads();
        if (j < 128) {
            u32 hi, lo;
            split2(sh[2 * j], sh[2 * j + 1], hi, lo);
            g_AH[bx * 132 + j] = hi;
            g_AL[bx * 132 + j] = lo;
        }
    } else if (bx == 64) {
        if (j < GHD) {
            for (int k = 0; k < GHD; k += 2) {
                u32 hi, lo;
                split2(Wg1[k * GHD + j], Wg1[(k + 1) * GHD + j], hi, lo);
                g_BH[j * 68 + (k >> 1)] = hi;
                g_BL[j * 68 + (k >> 1)] = lo;
            }
        }
    } else {
        __shared__ float sr1[GHD], sr2[GHD];
        if (j < GHD) {
            float w2o = 0.0f;
            for (int d = 0; d < GHD; d++)
                w2o = fmaf(Wg2[j * GHD + d], Wout[d], w2o);
            float gwv = g2[j] * w2o;
            g_gw[j] = gwv;
            sr1[j] = gwv;
            sr2[j] = b2ln[j] * w2o;
        }
        __syncthreads();
        if (j == 0) {
            float k1 = 0.0f, k2 = 0.0f;
            for (int i = 0; i < GHD; i++) { k1 += sr1[i]; k2 += sr2[i]; }
            g_K[0] = k1;
            g_K[1] = k2;
        }
    }
}

// ===========================================================================
// K_MEGA (3 blocks/SM): dispatch-ordered roles.
//  [0, 2048):    enc role — per-panel A+B staging, 2-stage double buffer,
//                fused 3-pass MMA; sets g_flag[bx].
//  [2048, 4288): gcn role — 64-row tile (60 outputs, halo 2); wait flags,
//                LN + full-N GEMM (B-image-major) + collapsed layer-2.
// ===========================================================================
// enc-role per-stage offsets (stage size 27648, 2 stages = 55296)
#define EP_ST   27648
#define EP_AH   0
#define EP_AL   5120
#define EP_BH   10240
#define EP_BL   18944
#define EAB     80                     // A panel row stride bytes
#define EBB     272                    // B panel row stride bytes
// gcn-role smem offsets
#define GSB     272
#define G_AHI   0
#define G_ALO   17408
#define G_BREG  34816                  // full-N B image (hi, then lo) / C tile
#define G_SMEM  69632

__global__ __launch_bounds__(256, 3) void k_mega(const float* __restrict__ W2,
                                                 const float* __restrict__ b2,
                                                 const float* __restrict__ Ah,
                                                 const float* __restrict__ g1,
                                                 const float* __restrict__ bb1,
                                                 const float* __restrict__ Wout,
                                                 const float* __restrict__ bout,
                                                 float* __restrict__ proj) {
    const int tid = threadIdx.x;
    const int L   = tid & 31;
    const int w   = tid >> 5;
    const u32 sb  = smem_u32(dynsm);

    if (blockIdx.x < N_ENC_BLK) {
        // ================= enc role =================
        const int j0 = blockIdx.x * 128;

        const int mw = w & 1, nw = w >> 1;
        const int R0 = mw * 32, N0 = nw * 32;
        const u32 arow = (u32)(L & 15);
        const u32 kcol = (u32)((L >> 4) << 3);
        const u32 brow = (u32)((L & 7) + ((L >> 3) & 1) * 8);
        const u32 bcol = (u32)((L >> 4) << 3);
        const int arow_i = tid >> 2, aq = tid & 3;   // A-panel copy mapping

        float acc[2][4][4];
#pragma unroll
        for (int mt = 0; mt < 2; mt++)
#pragma unroll
            for (int j = 0; j < 4; j++)
#pragma unroll
                for (int c = 0; c < 4; c++) acc[mt][j][c] = 0.0f;

        // prefetch panel 0
        uint4 pAh, pAl, pAh2, pAl2;
        float4 pB[4], pB2[4];
        pAh = ((const uint4*)g_AH)[arow_i * 33 + aq];
        pAl = ((const uint4*)g_AL)[arow_i * 33 + aq];
#pragma unroll
        for (int t = 0; t < 4; t++) {
            int i = tid + t * 256;
            int row = i >> 5, c4 = i & 31;
            pB[t] = *(const float4*)&W2[(size_t)row * JTOT + j0 + c4 * 4];
        }

        for (int kp = 0; kp < 8; kp++) {
            const u32 base = (u32)((kp & 1) * EP_ST);
            // store prefetched panel into this stage
            *(uint4*)(dynsm + base + EP_AH + arow_i * EAB + aq * 16) = pAh;
            *(uint4*)(dynsm + base + EP_AL + arow_i * EAB + aq * 16) = pAl;
#pragma unroll
            for (int t = 0; t < 4; t++) {
                int i = tid + t * 256;
                int row = i >> 5, c4 = i & 31;
                u32 h0, l0, h1, l1;
                split2(pB[t].x, pB[t].y, h0, l0);
                split2(pB[t].z, pB[t].w, h1, l1);
                *(uint2*)(dynsm + base + EP_BH + row * EBB + c4 * 8) =
                    make_uint2(h0, h1);
                *(uint2*)(dynsm + base + EP_BL + row * EBB + c4 * 8) =
                    make_uint2(l0, l1);
            }
            // issue next panel's global loads (latency hidden by MMA below)
            if (kp < 7) {
                pAh2 = ((const uint4*)g_AH)[arow_i * 33 + (kp + 1) * 4 + aq];
                pAl2 = ((const uint4*)g_AL)[arow_i * 33 + (kp + 1) * 4 + aq];
#pragma unroll
                for (int t = 0; t < 4; t++) {
                    int i = tid + t * 256;
                    int row = i >> 5, c4 = i & 31;
                    pB2[t] = *(const float4*)&W2[(size_t)((kp + 1) * 32 + row) * JTOT +
                                                 j0 + c4 * 4];
                }
            }
            __syncthreads();

            // ---- fused 3-pass MMA over this panel ----
#pragma unroll
            for (int ks = 0; ks < 2; ks++) {
                u32 ka = (u32)((ks * 16 + kcol) * 2);
                u32 ah0[4], ah1[4], al0[4], al1[4];
                ldsm4(ah0, sb + base + EP_AH + (R0 + arow) * EAB + ka);
                ldsm4(ah1, sb + base + EP_AH + (R0 + 16 + arow) * EAB + ka);
                ldsm4(al0, sb + base + EP_AL + (R0 + arow) * EAB + ka);
                ldsm4(al1, sb + base + EP_AL + (R0 + 16 + arow) * EAB + ka);
                u32 kb = (u32)((ks * 16 + brow) * EBB);
                u32 bf[2][4];
#pragma unroll
                for (int nt = 0; nt < 2; nt++)
                    ldsm4t(bf[nt], sb + base + EP_BH + kb + (N0 + nt * 16 + bcol) * 2);
#pragma unroll
                for (int j = 0; j < 4; j++) {
                    u32 b0 = bf[j >> 1][(j & 1) * 2];
                    u32 b1 = bf[j >> 1][(j & 1) * 2 + 1];
                    mma16816(acc[0][j], ah0, b0, b1);
                    mma16816(acc[1][j], ah1, b0, b1);
                    mma16816(acc[0][j], al0, b0, b1);
                    mma16816(acc[1][j], al1, b0, b1);
                }
#pragma unroll
                for (int nt = 0; nt < 2; nt++)
                    ldsm4t(bf[nt], sb + base + EP_BL + kb + (N0 + nt * 16 + bcol) * 2);
#pragma unroll
                for (int j = 0; j < 4; j++) {
                    u32 b0 = bf[j >> 1][(j & 1) * 2];
                    u32 b1 = bf[j >> 1][(j & 1) * 2 + 1];
                    mma16816(acc[0][j], ah0, b0, b1);
                    mma16816(acc[1][j], ah1, b0, b1);
                }
            }
            pAh = pAh2; pAl = pAl2;
#pragma unroll
            for (int t = 0; t < 4; t++) pB[t] = pB2[t];
        }

#pragma unroll
        for (int mt = 0; mt < 2; mt++) {
            int m = R0 + mt * 16 + (L >> 2);
#pragma unroll
            for (int j = 0; j < 4; j++) {
                int n = j0 + N0 + j * 8 + (L & 3) * 2;
                float b20 = __ldg(&b2[n]), b21 = __ldg(&b2[n + 1]);
                *(float2*)&g_buf0[(size_t)m * JTOT + n] =
                    make_float2(acc[mt][j][0] + b20, acc[mt][j][1] + b21);
                *(float2*)&g_buf0[(size_t)(m + 8) * JTOT + n] =
                    make_float2(acc[mt][j][2] + b20, acc[mt][j][3] + b21);
            }
        }

        __threadfence();
        __syncthreads();
        if (tid == 0) ((volatile int*)g_flag)[blockIdx.x] = 1;
        return;
    }

    // ================= gcn role (64-row tile) =================
    __shared__ float sAp[64], sAn[64], sT[64], sU[64];
    __shared__ float sG1[128], sB1[128], sWo[128], sGw[128];

    const int bx = blockIdx.x - N_ENC_BLK;
    const int nt = bx >> 6;                // 0..34
    const int b  = bx & 63;
    const int n0 = nt * 60;                // staged row r <-> gi = n0 - 2 + r

    if (tid < 128) {
        sG1[tid] = g1[tid];
        sB1[tid] = bb1[tid];
        sWo[tid] = Wout[tid];
        sGw[tid] = g_gw[tid];
    }
    if (tid < 64) {
        int gi = n0 - 2 + tid;
        sAp[tid] = (gi >= 1 && gi < NNODES) ? Ah[(size_t)gi * NNODES + gi - 1] : 0.0f;
        sAn[tid] = (gi >= 0 && gi < NNODES - 1) ? Ah[(size_t)gi * NNODES + gi + 1] : 0.0f;
    }

    // ---- stage Bhi full-N (no dependency on enc output) ----
    {
        uint4* dh = (uint4*)(dynsm + G_BREG);
        for (int i = tid; i < 2176; i += 256)
            dh[i] = ((const uint4*)g_BH)[i];
    }

    // ---- wait for the nodes this tile reads ----
    if (tid < 64) {
        int gi = min(NNODES - 1, max(0, n0 - 2 + tid));
        while (((volatile int*)g_flag)[gi] == 0) __nanosleep(128);
    }
    __threadfence();
    __syncthreads();

    // ---- LN1 + bf16 split -> A tiles (warp w owns rows {w+8t}, t<8) ----
    const int c0 = 2 * L, c2 = 64 + 2 * L;
#pragma unroll 4
    for (int t = 0; t < 8; t++) {
        int row = w + 8 * t;
        int gi  = min(NNODES - 1, max(0, n0 - 2 + row));
        const float* p = &g_buf0[((size_t)b * NNODES + gi) * GHD + c0];
        float2 v0 = *(const float2*)p;
        float2 v1 = *(const float2*)(p + 64);
        float s = v0.x + v0.y + v1.x + v1.y;
        float q = v0.x * v0.x + v0.y * v0.y + v1.x * v1.x + v1.y * v1.y;
#pragma unroll
        for (int o = 16; o; o >>= 1) {
            s += __shfl_xor_sync(0xFFFFFFFFu, s, o);
            q += __shfl_xor_sync(0xFFFFFFFFu, q, o);
        }
        float mu   = s * (1.0f / GHD);
        float rstd = rsqrtf(fmaxf(q * (1.0f / GHD) - mu * mu, 0.0f) + LN_EPS);
        float f0 = (v0.x - mu) * rstd * sG1[c0] + sB1[c0];
        float f1 = (v0.y - mu) * rstd * sG1[c0 + 1] + sB1[c0 + 1];
        float f2 = (v1.x - mu) * rstd * sG1[c2] + sB1[c2];
        float f3 = (v1.y - mu) * rstd * sG1[c2 + 1] + sB1[c2 + 1];
        u32 h0, l0, h1, l1;
        split2(f0, f1, h0, l0);
        split2(f2, f3, h1, l1);
        *(u32*)(dynsm + G_AHI + row * GSB + L * 4)       = h0;
        *(u32*)(dynsm + G_AHI + row * GSB + 128 + L * 4) = h1;
        *(u32*)(dynsm + G_ALO + row * GSB + L * 4)       = l0;
        *(u32*)(dynsm + G_ALO + row * GSB + 128 + L * 4) = l1;
    }
    __syncthreads();

    // ---- MMA: 64M x 128N, B-image-major pass order ----
    const int mw = w & 1, nh = w >> 1;     // warp tile 32M x 32N
    const int R0 = mw * 32, N0c = nh * 32;
    const u32 arow = (u32)(L & 15);
    const u32 kcol = (u32)((L >> 4) << 3);
    const float K1 = g_K[0], K2 = g_K[1];

    float acc[2][4][4];
#pragma unroll
    for (int mt = 0; mt < 2; mt++)
#pragma unroll
        for (int j = 0; j < 4; j++)
#pragma unroll
            for (int c = 0; c < 4; c++) acc[mt][j][c] = 0.0f;

    // Phase 1: (Ahi + Alo) * Bhi
#pragma unroll
    for (int ks = 0; ks < 8; ks++) {
        u32 kb = (u32)((ks * 16 + kcol) * 2);
        u32 ah0[4], ah1[4], al0[4], al1[4];
        ldsm4(ah0, sb + G_AHI + (R0 + arow) * GSB + kb);
        ldsm4(ah1, sb + G_AHI + (R0 + 16 + arow) * GSB + kb);
        ldsm4(al0, sb + G_ALO + (R0 + arow) * GSB + kb);
        ldsm4(al1, sb + G_ALO + (R0 + 16 + arow) * GSB + kb);
        u32 bf[2][4];
#pragma unroll
        for (int g = 0; g < 2; g++)
            ldsm4(bf[g], sb + G_BREG + (N0c + g * 16 + arow) * GSB + kb);
#pragma unroll
        for (int j = 0; j < 4; j++) {
            u32 b0 = bf[j >> 1][(j & 1)];
            u32 b1 = bf[j >> 1][(j & 1) + 2];
            mma16816(acc[0][j], ah0, b0, b1);
            mma16816(acc[1][j], ah1, b0, b1);
            mma16816(acc[0][j], al0, b0, b1);
            mma16816(acc[1][j], al1, b0, b1);
        }
    }
    __syncthreads();                       // Bhi reads done -> restage as Blo
    {
        uint4* dh = (uint4*)(dynsm + G_BREG);
        for (int i = tid; i < 2176; i += 256)
            dh[i] = ((const uint4*)g_BL)[i];
    }
    __syncthreads();

    // Phase 2: Ahi * Blo
#pragma unroll
    for (int ks = 0; ks < 8; ks++) {
        u32 kb = (u32)((ks * 16 + kcol) * 2);
        u32 ah0[4], ah1[4];
        ldsm4(ah0, sb + G_AHI + (R0 + arow) * GSB + kb);
        ldsm4(ah1, sb + G_AHI + (R0 + 16 + arow) * GSB + kb);
        u32 bf[2][4];
#pragma unroll
        for (int g = 0; g < 2; g++)
            ldsm4(bf[g], sb + G_BREG + (N0c + g * 16 + arow) * GSB + kb);
#pragma unroll
        for (int j = 0; j < 4; j++) {
            u32 b0 = bf[j >> 1][(j & 1)];
            u32 b1 = bf[j >> 1][(j & 1) + 2];
            mma16816(acc[0][j], ah0, b0, b1);
            mma16816(acc[1][j], ah1, b0, b1);
        }
    }
    __syncthreads();                       // A reads done -> A region becomes C

    // ---- C frags -> sC (A region, stride 136 floats) ----
    float* sC = (float*)(dynsm + G_AHI);
#pragma unroll
    for (int mt = 0; mt < 2; mt++) {
        int m = R0 + mt * 16 + (L >> 2);
        int n = N0c + (L & 3) * 2;
#pragma unroll
        for (int j = 0; j < 4; j++) {
            *(float2*)&sC[m * 136 + n + j * 8] =
                make_float2(acc[mt][j][0], acc[mt][j][1]);
            *(float2*)&sC[(m + 8) * 136 + n + j * 8] =
                make_float2(acc[mt][j][2], acc[mt][j][3]);
        }
    }
    __syncthreads();

    // ---- single full-width dot pass -> sT, sU (rows 1..62) ----
#pragma unroll 2
    for (int t = 0; t < 8; t++) {
        int row = w + 8 * t;
        if (row < 1 || row > 62) continue;
        int gi = min(NNODES - 1, max(0, n0 - 2 + row));
        const float* p = &g_buf0[((size_t)b * NNODES + gi) * GHD + c0];
        float2 iv0 = *(const float2*)p;
        float2 iv1 = *(const float2*)(p + 64);
        float2 wp0 = *(const float2*)&sC[(row - 1) * 136 + c0];
        float2 wp1 = *(const float2*)&sC[(row - 1) * 136 + c2];
        float2 wn0 = *(const float2*)&sC[(row + 1) * 136 + c0];
        float2 wn1 = *(const float2*)&sC[(row + 1) * 136 + c2];
        float ap = sAp[row], an = sAn[row];
        float o0 = fmaf(an, wn0.x, fmaf(ap, wp0.x, iv0.x));
        float o1 = fmaf(an, wn0.y, fmaf(ap, wp0.y, iv0.y));
        float o2 = fmaf(an, wn1.x, fmaf(ap, wp1.x, iv1.x));
        float o3 = fmaf(an, wn1.y, fmaf(ap, wp1.y, iv1.y));
        float sv = o0 + o1 + o2 + o3;
        float sq = o0 * o0 + o1 * o1 + o2 * o2 + o3 * o3;
        float st = o0 * sWo[c0] + o1 * sWo[c0 + 1] + o2 * sWo[c2] + o3 * sWo[c2 + 1];
        float sg = o0 * sGw[c0] + o1 * sGw[c0 + 1] + o2 * sGw[c2] + o3 * sGw[c2 + 1];
#pragma unroll
        for (int o = 16; o; o >>= 1) {
            sv += __shfl_xor_sync(0xFFFFFFFFu, sv, o);
            sq += __shfl_xor_sync(0xFFFFFFFFu, sq, o);
            st += __shfl_xor_sync(0xFFFFFFFFu, st, o);
            sg += __shfl_xor_sync(0xFFFFFFFFu, sg, o);
        }
        if (L == 0) {
            float mu   = sv * (1.0f / GHD);
            float rstd = rsqrtf(fmaxf(sq * (1.0f / GHD) - mu * mu, 0.0f) + LN_EPS);
            sT[row] = st;
            sU[row] = rstd * (sg - mu * K1) + K2;
        }
    }
    __syncthreads();

    // ---- final: rows 2..61 -> proj ----
    if (tid < 60) {
        int row = tid + 2;
        int gi  = n0 + tid;
        if (gi < NNODES) {
            float f = sT[row] + sAp[row] * sU[row - 1] + sAn[row] * sU[row + 1] +
                      bout[0];
            proj[b * NNODES + gi] = f;
        }
    }
}

// ===========================================================================
extern "C" void kernel_launch(void* const* d_in, const int* in_sizes, int n_in,
                              void* d_out, int out_size) {
    const float* x    = (const float*)d_in[0];
    const float* Ah   = (const float*)d_in[1];
    const float* W1   = (const float*)d_in[2];
    const float* b1   = (const float*)d_in[3];
    const float* W2   = (const float*)d_in[4];
    const float* b2   = (const float*)d_in[5];
    const float* Wg1  = (const float*)d_in[6];
    const float* Wg2  = (const float*)d_in[7];
    const float* g1   = (const float*)d_in[8];
    const float* bb1  = (const float*)d_in[9];
    const float* g2   = (const float*)d_in[10];
    const float* bb2  = (const float*)d_in[11];
    const float* Wout = (const float*)d_in[12];
    const float* bout = (const float*)d_in[13];
    float* out = (float*)d_out;

    cudaFuncSetAttribute(k_mega, cudaFuncAttributeMaxDynamicSharedMemorySize,
                         G_SMEM);

    k_init<<<66, ENC_HID>>>(x, W1, b1, Wg1, Wg2, Wout, g2, bb2);
    k_mega<<<N_ENC_BLK + N_GCN_BLK, 256, G_SMEM>>>(W2, b2, Ah, g1, bb1,
                                                   Wout, bout, out);
}

// round 15
// speedup vs baseline: 1.1997x; 1.1997x over previous
#include <cuda_runtime.h>
#include <cuda_bf16.h>

typedef unsigned int       u32;
typedef unsigned long long u64;

#define BSZ      64
#define ENC_IN   64
#define ENC_HID  256
#define NNODES   2048
#define GHD      128
#define JTOT     (NNODES * GHD)      // 262144
#define LN_EPS   1e-5f

#define N_ENC_BLK NNODES             // 2048 (one node per enc block)
#define N_GCN_BLK (17 * BSZ)         // 1088

// ---------------- scratch (device globals: allocation-guard safe) ----------
__device__ float g_h1[BSZ * ENC_HID];                  // [m][k] h1 rows
__device__ float g_buf0[(size_t)BSZ * NNODES * GHD];   // enc output
// A (=h1) bf16 hi/lo smem-image, row stride 528B (132 u32), 64 rows
__device__ __align__(16) u32 g_AH[64 * 132];
__device__ __align__(16) u32 g_AL[64 * 132];
// Wg1 transposed [n][k] bf16 hi/lo image, row stride 136 halfs (= 68 u32)
__device__ __align__(16) u32 g_BH[GHD * 68];
__device__ __align__(16) u32 g_BL[GHD * 68];
// layer-2 collapse: w2o = Wg2 @ Wout; gw = g2*w2o; K = {sum gw, sum b2*w2o}
__device__ float g_gw[GHD];
__device__ float g_K[2];
// per-node completion flags for producer/consumer safety
__device__ int g_flag[NNODES];

extern __shared__ __align__(1024) char dynsm[];

// ---------------- helpers ---------------------------------------------------
__device__ __forceinline__ u32 smem_u32(const void* p) {
    u32 a;
    asm("{ .reg .u64 t; cvta.to.shared.u64 t, %1; cvt.u32.u64 %0, t; }"
        : "=r"(a) : "l"(p));
    return a;
}
__device__ __forceinline__ void ldsm4(u32* r, u32 a) {
    asm volatile("ldmatrix.sync.aligned.m8n8.x4.shared.b16 {%0,%1,%2,%3}, [%4];"
                 : "=r"(r[0]), "=r"(r[1]), "=r"(r[2]), "=r"(r[3]) : "r"(a));
}
__device__ __forceinline__ void ldsm4t(u32* r, u32 a) {
    asm volatile("ldmatrix.sync.aligned.m8n8.x4.trans.shared.b16 {%0,%1,%2,%3}, [%4];"
                 : "=r"(r[0]), "=r"(r[1]), "=r"(r[2]), "=r"(r[3]) : "r"(a));
}
__device__ __forceinline__ void mma16816(float* c, const u32* a, u32 b0, u32 b1) {
    asm volatile(
        "mma.sync.aligned.m16n8k16.row.col.f32.bf16.bf16.f32 "
        "{%0,%1,%2,%3}, {%4,%5,%6,%7}, {%8,%9}, {%0,%1,%2,%3};"
        : "+f"(c[0]), "+f"(c[1]), "+f"(c[2]), "+f"(c[3])
        : "r"(a[0]), "r"(a[1]), "r"(a[2]), "r"(a[3]), "r"(b0), "r"(b1));
}
__device__ __forceinline__ void split2(float a, float b, u32& hi, u32& lo) {
    __nv_bfloat162 h = __floats2bfloat162_rn(a, b);
    float ha = __bfloat162float(h.x), hb = __bfloat162float(h.y);
    __nv_bfloat162 l = __floats2bfloat162_rn(a - ha, b - hb);
    hi = *reinterpret_cast<u32*>(&h);
    lo = *reinterpret_cast<u32*>(&l);
}

// ===========================================================================
// K_INIT (66 blocks): 0..63 flag reset + h1 + A-image row; 64 Wg1 image;
// 65 layer-2 collapse vectors.
// ===========================================================================
__global__ void k_init(const float* __restrict__ x,
                       const float* __restrict__ W1,
                       const float* __restrict__ b1,
                       const float* __restrict__ Wg1,
                       const float* __restrict__ Wg2,
                       const float* __restrict__ Wout,
                       const float* __restrict__ g2,
                       const float* __restrict__ b2ln) {
    const int bx = blockIdx.x;
    const int j  = threadIdx.x;
    if (bx < 64) {
        if (j < 32) g_flag[bx * 32 + j] = 0;
        __shared__ float sx[ENC_IN];
        __shared__ float sh[ENC_HID];
        if (j < ENC_IN) sx[j] = x[bx * ENC_IN + j];
        __syncthreads();
        float acc = b1[j];
#pragma unroll
        for (int k = 0; k < ENC_IN; k++)
            acc = fmaf(sx[k], W1[k * ENC_HID + j], acc);
        float h = fmaxf(acc, 0.0f);
        g_h1[bx * ENC_HID + j] = h;
        sh[j] = h;
        __syncthreads();
        if (j < 128) {
            u32 hi, lo;
            split2(sh[2 * j], sh[2 * j + 1], hi, lo);
            g_AH[bx * 132 + j] = hi;
            g_AL[bx * 132 + j] = lo;
        }
    } else if (bx == 64) {
        if (j < GHD) {
            for (int k = 0; k < GHD; k += 2) {
                u32 hi, lo;
                split2(Wg1[k * GHD + j], Wg1[(k + 1) * GHD + j], hi, lo);
                g_BH[j * 68 + (k >> 1)] = hi;
                g_BL[j * 68 + (k >> 1)] = lo;
            }
        }
    } else {
        __shared__ float sr1[GHD], sr2[GHD];
        if (j < GHD) {
            float w2o = 0.0f;
            for (int d = 0; d < GHD; d++)
                w2o = fmaf(Wg2[j * GHD + d], Wout[d], w2o);
            float gwv = g2[j] * w2o;
            g_gw[j] = gwv;
            sr1[j] = gwv;
            sr2[j] = b2ln[j] * w2o;
        }
        __syncthreads();
        if (j == 0) {
            float k1 = 0.0f, k2 = 0.0f;
            for (int i = 0; i < GHD; i++) { k1 += sr1[i]; k2 += sr2[i]; }
            g_K[0] = k1;
            g_K[1] = k2;
        }
    }
}

// ===========================================================================
// K_MEGA (R12 configuration — empirical optimum): dispatch-ordered roles.
//  [0, 2048):    enc role — full-K A image staged once, double-buffered B
//                panels, fused 3-pass MMA per k-step; sets g_flag[bx].
//  [2048, 3136): gcn role — 128-row tile; wait flags, LN + full-N GEMM
//                (B-image-major) + collapsed layer-2 + projection.
// ===========================================================================
// enc-role smem offsets
#define ESB       528
#define EBB       272
#define E_AHI     0
#define E_ALO     33792
#define E_B0HI    67584
#define E_B0LO    76288
#define E_B1HI    84992
#define E_B1LO    93696
// gcn-role smem offsets
#define GSB       272
#define G_AHI     0
#define G_ALO     34816
#define G_BREG    69632                    // full-N B image (hi, then lo) / C in A region
#define G_SMEM    104448

__global__ __launch_bounds__(256, 2) void k_mega(const float* __restrict__ W2,
                                                 const float* __restrict__ b2,
                                                 const float* __restrict__ Ah,
                                                 const float* __restrict__ g1,
                                                 const float* __restrict__ bb1,
                                                 const float* __restrict__ Wout,
                                                 const float* __restrict__ bout,
                                                 float* __restrict__ proj) {
    const int tid = threadIdx.x;
    const int L   = tid & 31;
    const int w   = tid >> 5;
    const u32 sb  = smem_u32(dynsm);

    if (blockIdx.x < N_ENC_BLK) {
        // ================= enc role =================
        const int j0 = blockIdx.x * 128;

        // ---- stage A image (linear uint4 copies; layout pre-baked) ----
        {
            uint4* dh = (uint4*)(dynsm + E_AHI);
            uint4* dl = (uint4*)(dynsm + E_ALO);
            const uint4* shp = (const uint4*)g_AH;
            const uint4* slp = (const uint4*)g_AL;
            for (int i = tid; i < 2112; i += 256) {
                dh[i] = shp[i];
                dl[i] = slp[i];
            }
        }

        const int mw = w & 1, nw = w >> 1;
        const int R0 = mw * 32, N0 = nw * 32;
        const u32 arow = (u32)(L & 15);
        const u32 kcol = (u32)((L >> 4) << 3);
        const u32 brow = (u32)((L & 7) + ((L >> 3) & 1) * 8);
        const u32 bcol = (u32)((L >> 4) << 3);

        float acc[2][4][4];
#pragma unroll
        for (int mt = 0; mt < 2; mt++)
#pragma unroll
            for (int j = 0; j < 4; j++)
#pragma unroll
                for (int c = 0; c < 4; c++) acc[mt][j][c] = 0.0f;

        // prefetch panel 0 (4 float4/thread: 32x128 floats)
        float4 pf[4], pf2[4];
#pragma unroll
        for (int t = 0; t < 4; t++) {
            int i = tid + t * 256;
            int row = i >> 5, c4 = i & 31;
            pf[t] = *(const float4*)&W2[(size_t)row * JTOT + j0 + c4 * 4];
        }

        for (int kp = 0; kp < 8; kp++) {
            const u32 bHI = (kp & 1) ? E_B1HI : E_B0HI;
            const u32 bLO = (kp & 1) ? E_B1LO : E_B0LO;
            // issue next panel's global loads first (hide latency under all below)
            if (kp < 7) {
#pragma unroll
                for (int t = 0; t < 4; t++) {
                    int i = tid + t * 256;
                    int row = i >> 5, c4 = i & 31;
                    pf2[t] = *(const float4*)&W2[(size_t)((kp + 1) * 32 + row) * JTOT +
                                                 j0 + c4 * 4];
                }
            }
            // convert current panel -> this stage (other stage may still be in MMA)
#pragma unroll
            for (int t = 0; t < 4; t++) {
                int i = tid + t * 256;
                int row = i >> 5, c4 = i & 31;
                u32 h0, l0, h1, l1;
                split2(pf[t].x, pf[t].y, h0, l0);
                split2(pf[t].z, pf[t].w, h1, l1);
                *(uint2*)(dynsm + bHI + row * EBB + c4 * 8) = make_uint2(h0, h1);
                *(uint2*)(dynsm + bLO + row * EBB + c4 * 8) = make_uint2(l0, l1);
            }
            __syncthreads();

            // ---- fused 3-pass MMA over this panel ----
#pragma unroll
            for (int ks = 0; ks < 2; ks++) {
                u32 ka = (u32)((kp * 32 + ks * 16 + kcol) * 2);
                u32 ah0[4], ah1[4], al0[4], al1[4];
                ldsm4(ah0, sb + E_AHI + (R0 + arow) * ESB + ka);
                ldsm4(ah1, sb + E_AHI + (R0 + 16 + arow) * ESB + ka);
                ldsm4(al0, sb + E_ALO + (R0 + arow) * ESB + ka);
                ldsm4(al1, sb + E_ALO + (R0 + 16 + arow) * ESB + ka);
                u32 kb = (u32)((ks * 16 + brow) * EBB);
                u32 bh[2][4], bl[2][4];
#pragma unroll
                for (int nt = 0; nt < 2; nt++) {
                    ldsm4t(bh[nt], sb + bHI + kb + (N0 + nt * 16 + bcol) * 2);
                    ldsm4t(bl[nt], sb + bLO + kb + (N0 + nt * 16 + bcol) * 2);
                }
#pragma unroll
                for (int j = 0; j < 4; j++) {
                    u32 b0 = bh[j >> 1][(j & 1) * 2];
                    u32 b1 = bh[j >> 1][(j & 1) * 2 + 1];
                    mma16816(acc[0][j], ah0, b0, b1);
                    mma16816(acc[1][j], ah1, b0, b1);
                    mma16816(acc[0][j], al0, b0, b1);
                    mma16816(acc[1][j], al1, b0, b1);
                    u32 c0v = bl[j >> 1][(j & 1) * 2];
                    u32 c1v = bl[j >> 1][(j & 1) * 2 + 1];
                    mma16816(acc[0][j], ah0, c0v, c1v);
                    mma16816(acc[1][j], ah1, c0v, c1v);
                }
            }
#pragma unroll
            for (int t = 0; t < 4; t++) pf[t] = pf2[t];
        }

        // ---- epilogue (b2 loads hoisted across mt) ----
        {
            int n = j0 + N0 + (L & 3) * 2;
            float b2v[4][2];
#pragma unroll
            for (int j = 0; j < 4; j++) {
                b2v[j][0] = __ldg(&b2[n + j * 8]);
                b2v[j][1] = __ldg(&b2[n + j * 8 + 1]);
            }
#pragma unroll
            for (int mt = 0; mt < 2; mt++) {
                int m = R0 + mt * 16 + (L >> 2);
#pragma unroll
                for (int j = 0; j < 4; j++) {
                    *(float2*)&g_buf0[(size_t)m * JTOT + n + j * 8] =
                        make_float2(acc[mt][j][0] + b2v[j][0],
                                    acc[mt][j][1] + b2v[j][1]);
                    *(float2*)&g_buf0[(size_t)(m + 8) * JTOT + n + j * 8] =
                        make_float2(acc[mt][j][2] + b2v[j][0],
                                    acc[mt][j][3] + b2v[j][1]);
                }
            }
        }

        __threadfence();
        __syncthreads();
        if (tid == 0) ((volatile int*)g_flag)[blockIdx.x] = 1;
        return;
    }

    // ================= gcn role =================
    __shared__ float sAp[128], sAn[128];
    __shared__ float sG1[128], sB1[128], sWo[128], sGw[128];
    __shared__ float sT[128], sU[128];

    const int bx = blockIdx.x - N_ENC_BLK;
    const int nt = bx >> 6;                // 0..16
    const int b  = bx & 63;
    const int n0 = nt * 124;               // staged row r <-> gi = n0 - 2 + r

    if (tid < 128) {
        sG1[tid] = g1[tid];
        sB1[tid] = bb1[tid];
        sWo[tid] = Wout[tid];
        sGw[tid] = g_gw[tid];
        int gi = n0 - 2 + tid;
        sAp[tid] = (gi >= 1 && gi < NNODES) ? Ah[(size_t)gi * NNODES + gi - 1] : 0.0f;
        sAn[tid] = (gi >= 0 && gi < NNODES - 1) ? Ah[(size_t)gi * NNODES + gi + 1] : 0.0f;
    }

    // ---- stage Bhi full-N (no dependency on enc output) ----
    {
        uint4* dh = (uint4*)(dynsm + G_BREG);
        for (int i = tid; i < 2176; i += 256)
            dh[i] = ((const uint4*)g_BH)[i];
    }

    // ---- wait for the nodes this tile reads ----
    if (tid < 128) {
        int gi = min(NNODES - 1, max(0, n0 - 2 + tid));
        while (((volatile int*)g_flag)[gi] == 0) __nanosleep(128);
    }
    __threadfence();
    __syncthreads();

    // ---- LN1 + bf16 split -> A tiles (warp w owns rows {w+8t}) ----
    const int c0 = 2 * L, c2 = 64 + 2 * L;
#pragma unroll 4
    for (int t = 0; t < 16; t++) {
        int row = w + 8 * t;
        int gi  = min(NNODES - 1, max(0, n0 - 2 + row));
        const float* p = &g_buf0[((size_t)b * NNODES + gi) * GHD + c0];
        float2 v0 = *(const float2*)p;
        float2 v1 = *(const float2*)(p + 64);
        float s = v0.x + v0.y + v1.x + v1.y;
        float q = v0.x * v0.x + v0.y * v0.y + v1.x * v1.x + v1.y * v1.y;
#pragma unroll
        for (int o = 16; o; o >>= 1) {
            s += __shfl_xor_sync(0xFFFFFFFFu, s, o);
            q += __shfl_xor_sync(0xFFFFFFFFu, q, o);
        }
        float mu   = s * (1.0f / GHD);
        float rstd = rsqrtf(fmaxf(q * (1.0f / GHD) - mu * mu, 0.0f) + LN_EPS);
        float f0 = (v0.x - mu) * rstd * sG1[c0] + sB1[c0];
        float f1 = (v0.y - mu) * rstd * sG1[c0 + 1] + sB1[c0 + 1];
        float f2 = (v1.x - mu) * rstd * sG1[c2] + sB1[c2];
        float f3 = (v1.y - mu) * rstd * sG1[c2 + 1] + sB1[c2 + 1];
        u32 h0, l0, h1, l1;
        split2(f0, f1, h0, l0);
        split2(f2, f3, h1, l1);
        *(u32*)(dynsm + G_AHI + row * GSB + L * 4)       = h0;
        *(u32*)(dynsm + G_AHI + row * GSB + 128 + L * 4) = h1;
        *(u32*)(dynsm + G_ALO + row * GSB + L * 4)       = l0;
        *(u32*)(dynsm + G_ALO + row * GSB + 128 + L * 4) = l1;
    }
    __syncthreads();

    // ---- MMA: full N=128, B-image-major pass order ----
    const int mw = w & 3, nh = w >> 2;
    const int R0 = mw * 32;
    const u32 arow = (u32)(L & 15);
    const u32 kcol = (u32)((L >> 4) << 3);
    const float K1 = g_K[0], K2 = g_K[1];

    float acc[2][2][4][4];                 // [ns][mt][j][c]
#pragma unroll
    for (int ns = 0; ns < 2; ns++)
#pragma unroll
        for (int mt = 0; mt < 2; mt++)
#pragma unroll
            for (int j = 0; j < 4; j++)
#pragma unroll
                for (int c = 0; c < 4; c++) acc[ns][mt][j][c] = 0.0f;

    // Phase 1: (Ahi + Alo) * Bhi
#pragma unroll
    for (int ks = 0; ks < 8; ks++) {
        u32 kb = (u32)((ks * 16 + kcol) * 2);
        u32 ah0[4], ah1[4], al0[4], al1[4];
        ldsm4(ah0, sb + G_AHI + (R0 + arow) * GSB + kb);
        ldsm4(ah1, sb + G_AHI + (R0 + 16 + arow) * GSB + kb);
        ldsm4(al0, sb + G_ALO + (R0 + arow) * GSB + kb);
        ldsm4(al1, sb + G_ALO + (R0 + 16 + arow) * GSB + kb);
#pragma unroll
        for (int ns = 0; ns < 2; ns++) {
            int N0 = nh * 32 + ns * 64;
            u32 bf[2][4];
#pragma unroll
            for (int g = 0; g < 2; g++)
                ldsm4(bf[g], sb + G_BREG + (N0 + g * 16 + arow) * GSB + kb);
#pragma unroll
            for (int j = 0; j < 4; j++) {
                u32 b0 = bf[j >> 1][(j & 1)];
                u32 b1 = bf[j >> 1][(j & 1) + 2];
                mma16816(acc[ns][0][j], ah0, b0, b1);
                mma16816(acc[ns][1][j], ah1, b0, b1);
                mma16816(acc[ns][0][j], al0, b0, b1);
                mma16816(acc[ns][1][j], al1, b0, b1);
            }
        }
    }
    __syncthreads();                       // Bhi reads done -> restage as Blo
    {
        uint4* dh = (uint4*)(dynsm + G_BREG);
        for (int i = tid; i < 2176; i += 256)
            dh[i] = ((const uint4*)g_BL)[i];
    }
    __syncthreads();

    // Phase 2: Ahi * Blo
#pragma unroll
    for (int ks = 0; ks < 8; ks++) {
        u32 kb = (u32)((ks * 16 + kcol) * 2);
        u32 ah0[4], ah1[4];
        ldsm4(ah0, sb + G_AHI + (R0 + arow) * GSB + kb);
        ldsm4(ah1, sb + G_AHI + (R0 + 16 + arow) * GSB + kb);
#pragma unroll
        for (int ns = 0; ns < 2; ns++) {
            int N0 = nh * 32 + ns * 64;
            u32 bf[2][4];
#pragma unroll
            for (int g = 0; g < 2; g++)
                ldsm4(bf[g], sb + G_BREG + (N0 + g * 16 + arow) * GSB + kb);
#pragma unroll
            for (int j = 0; j < 4; j++) {
                u32 b0 = bf[j >> 1][(j & 1)];
                u32 b1 = bf[j >> 1][(j & 1) + 2];
                mma16816(acc[ns][0][j], ah0, b0, b1);
                mma16816(acc[ns][1][j], ah1, b0, b1);
            }
        }
    }
    __syncthreads();                       // A reads done -> A region becomes C

    // ---- C frags -> sC (A region, stride 136 floats) ----
    float* sC = (float*)(dynsm + G_AHI);
#pragma unroll
    for (int ns = 0; ns < 2; ns++) {
#pragma unroll
        for (int mt = 0; mt < 2; mt++) {
            int m = R0 + mt * 16 + (L >> 2);
            int n = nh * 32 + ns * 64 + (L & 3) * 2;
#pragma unroll
            for (int j = 0; j < 4; j++) {
                *(float2*)&sC[m * 136 + n + j * 8] =
                    make_float2(acc[ns][mt][j][0], acc[ns][mt][j][1]);
                *(float2*)&sC[(m + 8) * 136 + n + j * 8] =
                    make_float2(acc[ns][mt][j][2], acc[ns][mt][j][3]);
            }
        }
    }
    __syncthreads();

    // ---- single full-width dot pass -> sT, sU ----
#pragma unroll 2
    for (int t = 0; t < 16; t++) {
        int row = w + 8 * t;
        if (row < 1 || row > 126) continue;
        int gi = min(NNODES - 1, max(0, n0 - 2 + row));
        const float* p = &g_buf0[((size_t)b * NNODES + gi) * GHD + c0];
        float2 iv0 = *(const float2*)p;
        float2 iv1 = *(const float2*)(p + 64);
        float2 wp0 = *(const float2*)&sC[(row - 1) * 136 + c0];
        float2 wp1 = *(const float2*)&sC[(row - 1) * 136 + c2];
        float2 wn0 = *(const float2*)&sC[(row + 1) * 136 + c0];
        float2 wn1 = *(const float2*)&sC[(row + 1) * 136 + c2];
        float ap = sAp[row], an = sAn[row];
        float o0 = fmaf(an, wn0.x, fmaf(ap, wp0.x, iv0.x));
        float o1 = fmaf(an, wn0.y, fmaf(ap, wp0.y, iv0.y));
        float o2 = fmaf(an, wn1.x, fmaf(ap, wp1.x, iv1.x));
        float o3 = fmaf(an, wn1.y, fmaf(ap, wp1.y, iv1.y));
        float sv = o0 + o1 + o2 + o3;
        float sq = o0 * o0 + o1 * o1 + o2 * o2 + o3 * o3;
        float st = o0 * sWo[c0] + o1 * sWo[c0 + 1] + o2 * sWo[c2] + o3 * sWo[c2 + 1];
        float sg = o0 * sGw[c0] + o1 * sGw[c0 + 1] + o2 * sGw[c2] + o3 * sGw[c2 + 1];
#pragma unroll
        for (int o = 16; o; o >>= 1) {
            sv += __shfl_xor_sync(0xFFFFFFFFu, sv, o);
            sq += __shfl_xor_sync(0xFFFFFFFFu, sq, o);
            st += __shfl_xor_sync(0xFFFFFFFFu, st, o);
            sg += __shfl_xor_sync(0xFFFFFFFFu, sg, o);
        }
        if (L == 0) {
            float mu   = sv * (1.0f / GHD);
            float rstd = rsqrtf(fmaxf(sq * (1.0f / GHD) - mu * mu, 0.0f) + LN_EPS);
            sT[row] = st;
            sU[row] = rstd * (sg - mu * K1) + K2;
        }
    }
    __syncthreads();

    // ---- final: rows 2..125 -> proj ----
    if (tid < 124) {
        int row = tid + 2;
        int gi  = n0 + tid;
        if (gi < NNODES) {
            float f = sT[row] + sAp[row] * sU[row - 1] + sAn[row] * sU[row + 1] +
                      bout[0];
            proj[b * NNODES + gi] = f;
        }
    }
}

// ===========================================================================
extern "C" void kernel_launch(void* const* d_in, const int* in_sizes, int n_in,
                              void* d_out, int out_size) {
    const float* x    = (const float*)d_in[0];
    const float* Ah   = (const float*)d_in[1];
    const float* W1   = (const float*)d_in[2];
    const float* b1   = (const float*)d_in[3];
    const float* W2   = (const float*)d_in[4];
    const float* b2   = (const float*)d_in[5];
    const float* Wg1  = (const float*)d_in[6];
    const float* Wg2  = (const float*)d_in[7];
    const float* g1   = (const float*)d_in[8];
    const float* bb1  = (const float*)d_in[9];
    const float* g2   = (const float*)d_in[10];
    const float* bb2  = (const float*)d_in[11];
    const float* Wout = (const float*)d_in[12];
    const float* bout = (const float*)d_in[13];
    float* out = (float*)d_out;

    cudaFuncSetAttribute(k_mega, cudaFuncAttributeMaxDynamicSharedMemorySize,
                         G_SMEM);

    k_init<<<66, ENC_HID>>>(x, W1, b1, Wg1, Wg2, Wout, g2, bb2);
    k_mega<<<N_ENC_BLK + N_GCN_BLK, 256, G_SMEM>>>(W2, b2, Ah, g1, bb1,
                                                   Wout, bout, out);
}

// round 16
// speedup vs baseline: 1.2518x; 1.0434x over previous
#include <cuda_runtime.h>
#include <cuda_bf16.h>

typedef unsigned int       u32;
typedef unsigned long long u64;

#define BSZ      64
#define ENC_IN   64
#define ENC_HID  256
#define NNODES   2048
#define GHD      128
#define JTOT     (NNODES * GHD)      // 262144
#define LN_EPS   1e-5f

#define N_ENC_BLK NNODES             // enc units (one node each)
#define N_GCN_BLK (17 * BSZ)         // 1088 gcn units
#define N_UNITS   (N_ENC_BLK + N_GCN_BLK)
#define N_PERS    304                // persistent blocks (152 SMs x 2)

// ---------------- scratch (device globals: allocation-guard safe) ----------
__device__ float g_h1[BSZ * ENC_HID];                  // [m][k] h1 rows
__device__ float g_buf0[(size_t)BSZ * NNODES * GHD];   // enc output
// A (=h1) bf16 hi/lo smem-image, row stride 528B (132 u32), 64 rows
__device__ __align__(16) u32 g_AH[64 * 132];
__device__ __align__(16) u32 g_AL[64 * 132];
// Wg1 transposed [n][k] bf16 hi/lo image, row stride 136 halfs (= 68 u32)
__device__ __align__(16) u32 g_BH[GHD * 68];
__device__ __align__(16) u32 g_BL[GHD * 68];
// layer-2 collapse: w2o = Wg2 @ Wout; gw = g2*w2o; K = {sum gw, sum b2*w2o}
__device__ float g_gw[GHD];
__device__ float g_K[2];
// per-node completion flags + work-queue ticket
__device__ int g_flag[NNODES];
__device__ int g_ticket;

extern __shared__ __align__(1024) char dynsm[];

// ---------------- helpers ---------------------------------------------------
__device__ __forceinline__ u32 smem_u32(const void* p) {
    u32 a;
    asm("{ .reg .u64 t; cvta.to.shared.u64 t, %1; cvt.u32.u64 %0, t; }"
        : "=r"(a) : "l"(p));
    return a;
}
__device__ __forceinline__ void ldsm4(u32* r, u32 a) {
    asm volatile("ldmatrix.sync.aligned.m8n8.x4.shared.b16 {%0,%1,%2,%3}, [%4];"
                 : "=r"(r[0]), "=r"(r[1]), "=r"(r[2]), "=r"(r[3]) : "r"(a));
}
__device__ __forceinline__ void ldsm4t(u32* r, u32 a) {
    asm volatile("ldmatrix.sync.aligned.m8n8.x4.trans.shared.b16 {%0,%1,%2,%3}, [%4];"
                 : "=r"(r[0]), "=r"(r[1]), "=r"(r[2]), "=r"(r[3]) : "r"(a));
}
__device__ __forceinline__ void mma16816(float* c, const u32* a, u32 b0, u32 b1) {
    asm volatile(
        "mma.sync.aligned.m16n8k16.row.col.f32.bf16.bf16.f32 "
        "{%0,%1,%2,%3}, {%4,%5,%6,%7}, {%8,%9}, {%0,%1,%2,%3};"
        : "+f"(c[0]), "+f"(c[1]), "+f"(c[2]), "+f"(c[3])
        : "r"(a[0]), "r"(a[1]), "r"(a[2]), "r"(a[3]), "r"(b0), "r"(b1));
}
__device__ __forceinline__ void split2(float a, float b, u32& hi, u32& lo) {
    __nv_bfloat162 h = __floats2bfloat162_rn(a, b);
    float ha = __bfloat162float(h.x), hb = __bfloat162float(h.y);
    __nv_bfloat162 l = __floats2bfloat162_rn(a - ha, b - hb);
    hi = *reinterpret_cast<u32*>(&h);
    lo = *reinterpret_cast<u32*>(&l);
}

// ===========================================================================
// K_INIT (66 blocks): 0..63 flag reset + h1 + A-image row; 64 Wg1 image +
// ticket reset; 65 layer-2 collapse vectors.
// ===========================================================================
__global__ void k_init(const float* __restrict__ x,
                       const float* __restrict__ W1,
                       const float* __restrict__ b1,
                       const float* __restrict__ Wg1,
                       const float* __restrict__ Wg2,
                       const float* __restrict__ Wout,
                       const float* __restrict__ g2,
                       const float* __restrict__ b2ln) {
    const int bx = blockIdx.x;
    const int j  = threadIdx.x;
    if (bx < 64) {
        if (j < 32) g_flag[bx * 32 + j] = 0;
        __shared__ float sx[ENC_IN];
        __shared__ float sh[ENC_HID];
        if (j < ENC_IN) sx[j] = x[bx * ENC_IN + j];
        __syncthreads();
        float acc = b1[j];
#pragma unroll
        for (int k = 0; k < ENC_IN; k++)
            acc = fmaf(sx[k], W1[k * ENC_HID + j], acc);
        float h = fmaxf(acc, 0.0f);
        g_h1[bx * ENC_HID + j] = h;
        sh[j] = h;
        __syncthreads();
        if (j < 128) {
            u32 hi, lo;
            split2(sh[2 * j], sh[2 * j + 1], hi, lo);
            g_AH[bx * 132 + j] = hi;
            g_AL[bx * 132 + j] = lo;
        }
    } else if (bx == 64) {
        if (j == 0) g_ticket = 0;
        if (j < GHD) {
            for (int k = 0; k < GHD; k += 2) {
                u32 hi, lo;
                split2(Wg1[k * GHD + j], Wg1[(k + 1) * GHD + j], hi, lo);
                g_BH[j * 68 + (k >> 1)] = hi;
                g_BL[j * 68 + (k >> 1)] = lo;
            }
        }
    } else {
        __shared__ float sr1[GHD], sr2[GHD];
        if (j < GHD) {
            float w2o = 0.0f;
            for (int d = 0; d < GHD; d++)
                w2o = fmaf(Wg2[j * GHD + d], Wout[d], w2o);
            float gwv = g2[j] * w2o;
            g_gw[j] = gwv;
            sr1[j] = gwv;
            sr2[j] = b2ln[j] * w2o;
        }
        __syncthreads();
        if (j == 0) {
            float k1 = 0.0f, k2 = 0.0f;
            for (int i = 0; i < GHD; i++) { k1 += sr1[i]; k2 += sr2[i]; }
            g_K[0] = k1;
            g_K[1] = k2;
        }
    }
}

// ===========================================================================
// K_MEGA — persistent work-queue version of the R12/R15 optimum.
// 304 persistent blocks; atomic ticket over 3136 units:
//   unit < 2048:  enc unit (node = unit). A-image staged ONCE per block.
//   unit >= 2048: gcn unit (tile, batch). Monotonic ticket => once a block
//                 runs a gcn unit (clobbering the A region) no enc unit can
//                 follow. gcn never blocks producers: all enc tickets are
//                 claimed before any gcn ticket exists.
// ===========================================================================
// enc-role smem offsets
#define ESB       528
#define EBB       272
#define E_AHI     0
#define E_ALO     33792
#define E_B0HI    67584
#define E_B0LO    76288
#define E_B1HI    84992
#define E_B1LO    93696
// gcn-role smem offsets
#define GSB       272
#define G_AHI     0
#define G_ALO     34816
#define G_BREG    69632                    // full-N B image (hi, then lo) / C in A region
#define G_SMEM    104448

__global__ __launch_bounds__(256, 2) void k_mega(const float* __restrict__ W2,
                                                 const float* __restrict__ b2,
                                                 const float* __restrict__ Ah,
                                                 const float* __restrict__ g1,
                                                 const float* __restrict__ bb1,
                                                 const float* __restrict__ Wout,
                                                 const float* __restrict__ bout,
                                                 float* __restrict__ proj) {
    __shared__ float sAp[128], sAn[128];
    __shared__ float sG1[128], sB1[128], sWo[128], sGw[128];
    __shared__ float sT[128], sU[128];
    __shared__ int s_u;

    const int tid = threadIdx.x;
    const int L   = tid & 31;
    const int w   = tid >> 5;
    const u32 sb  = smem_u32(dynsm);

    // ---- stage A image once per persistent block ----
    {
        uint4* dh = (uint4*)(dynsm + E_AHI);
        uint4* dl = (uint4*)(dynsm + E_ALO);
        const uint4* shp = (const uint4*)g_AH;
        const uint4* slp = (const uint4*)g_AL;
        for (int i = tid; i < 2112; i += 256) {
            dh[i] = shp[i];
            dl[i] = slp[i];
        }
    }
    __syncthreads();

    for (;;) {
        if (tid == 0) s_u = atomicAdd(&g_ticket, 1);
        __syncthreads();
        const int u = s_u;
        if (u >= N_UNITS) break;

        if (u < N_ENC_BLK) {
            // ================= enc unit =================
            const int j0 = u * 128;

            const int mw = w & 1, nw = w >> 1;
            const int R0 = mw * 32, N0 = nw * 32;
            const u32 arow = (u32)(L & 15);
            const u32 kcol = (u32)((L >> 4) << 3);
            const u32 brow = (u32)((L & 7) + ((L >> 3) & 1) * 8);
            const u32 bcol = (u32)((L >> 4) << 3);

            float acc[2][4][4];
#pragma unroll
            for (int mt = 0; mt < 2; mt++)
#pragma unroll
                for (int j = 0; j < 4; j++)
#pragma unroll
                    for (int c = 0; c < 4; c++) acc[mt][j][c] = 0.0f;

            float4 pf[4], pf2[4];
#pragma unroll
            for (int t = 0; t < 4; t++) {
                int i = tid + t * 256;
                int row = i >> 5, c4 = i & 31;
                pf[t] = *(const float4*)&W2[(size_t)row * JTOT + j0 + c4 * 4];
            }

            for (int kp = 0; kp < 8; kp++) {
                const u32 bHI = (kp & 1) ? E_B1HI : E_B0HI;
                const u32 bLO = (kp & 1) ? E_B1LO : E_B0LO;
                if (kp < 7) {
#pragma unroll
                    for (int t = 0; t < 4; t++) {
                        int i = tid + t * 256;
                        int row = i >> 5, c4 = i & 31;
                        pf2[t] = *(const float4*)&W2[
                            (size_t)((kp + 1) * 32 + row) * JTOT + j0 + c4 * 4];
                    }
                }
#pragma unroll
                for (int t = 0; t < 4; t++) {
                    int i = tid + t * 256;
                    int row = i >> 5, c4 = i & 31;
                    u32 h0, l0, h1, l1;
                    split2(pf[t].x, pf[t].y, h0, l0);
                    split2(pf[t].z, pf[t].w, h1, l1);
                    *(uint2*)(dynsm + bHI + row * EBB + c4 * 8) = make_uint2(h0, h1);
                    *(uint2*)(dynsm + bLO + row * EBB + c4 * 8) = make_uint2(l0, l1);
                }
                __syncthreads();

#pragma unroll
                for (int ks = 0; ks < 2; ks++) {
                    u32 ka = (u32)((kp * 32 + ks * 16 + kcol) * 2);
                    u32 ah0[4], ah1[4], al0[4], al1[4];
                    ldsm4(ah0, sb + E_AHI + (R0 + arow) * ESB + ka);
                    ldsm4(ah1, sb + E_AHI + (R0 + 16 + arow) * ESB + ka);
                    ldsm4(al0, sb + E_ALO + (R0 + arow) * ESB + ka);
                    ldsm4(al1, sb + E_ALO + (R0 + 16 + arow) * ESB + ka);
                    u32 kb = (u32)((ks * 16 + brow) * EBB);
                    u32 bh[2][4], bl[2][4];
#pragma unroll
                    for (int nt = 0; nt < 2; nt++) {
                        ldsm4t(bh[nt], sb + bHI + kb + (N0 + nt * 16 + bcol) * 2);
                        ldsm4t(bl[nt], sb + bLO + kb + (N0 + nt * 16 + bcol) * 2);
                    }
#pragma unroll
                    for (int j = 0; j < 4; j++) {
                        u32 b0 = bh[j >> 1][(j & 1) * 2];
                        u32 b1 = bh[j >> 1][(j & 1) * 2 + 1];
                        mma16816(acc[0][j], ah0, b0, b1);
                        mma16816(acc[1][j], ah1, b0, b1);
                        mma16816(acc[0][j], al0, b0, b1);
                        mma16816(acc[1][j], al1, b0, b1);
                        u32 c0v = bl[j >> 1][(j & 1) * 2];
                        u32 c1v = bl[j >> 1][(j & 1) * 2 + 1];
                        mma16816(acc[0][j], ah0, c0v, c1v);
                        mma16816(acc[1][j], ah1, c0v, c1v);
                    }
                }
#pragma unroll
                for (int t = 0; t < 4; t++) pf[t] = pf2[t];
            }

            // ---- epilogue ----
            {
                int n = j0 + N0 + (L & 3) * 2;
                float b2v[4][2];
#pragma unroll
                for (int j = 0; j < 4; j++) {
                    b2v[j][0] = __ldg(&b2[n + j * 8]);
                    b2v[j][1] = __ldg(&b2[n + j * 8 + 1]);
                }
#pragma unroll
                for (int mt = 0; mt < 2; mt++) {
                    int m = R0 + mt * 16 + (L >> 2);
#pragma unroll
                    for (int j = 0; j < 4; j++) {
                        *(float2*)&g_buf0[(size_t)m * JTOT + n + j * 8] =
                            make_float2(acc[mt][j][0] + b2v[j][0],
                                        acc[mt][j][1] + b2v[j][1]);
                        *(float2*)&g_buf0[(size_t)(m + 8) * JTOT + n + j * 8] =
                            make_float2(acc[mt][j][2] + b2v[j][0],
                                        acc[mt][j][3] + b2v[j][1]);
                    }
                }
            }

            __threadfence();
            __syncthreads();
            if (tid == 0) ((volatile int*)g_flag)[u] = 1;
        } else {
            // ================= gcn unit =================
            const int bx = u - N_ENC_BLK;
            const int nt = bx >> 6;            // 0..16
            const int b  = bx & 63;
            const int n0 = nt * 124;           // staged row r <-> gi = n0 - 2 + r

            if (tid < 128) {
                sG1[tid] = g1[tid];
                sB1[tid] = bb1[tid];
                sWo[tid] = Wout[tid];
                sGw[tid] = g_gw[tid];
                int gi = n0 - 2 + tid;
                sAp[tid] = (gi >= 1 && gi < NNODES)
                               ? Ah[(size_t)gi * NNODES + gi - 1] : 0.0f;
                sAn[tid] = (gi >= 0 && gi < NNODES - 1)
                               ? Ah[(size_t)gi * NNODES + gi + 1] : 0.0f;
            }

            // ---- stage Bhi full-N ----
            {
                uint4* dh = (uint4*)(dynsm + G_BREG);
                for (int i = tid; i < 2176; i += 256)
                    dh[i] = ((const uint4*)g_BH)[i];
            }

            // ---- wait for the nodes this tile reads ----
            if (tid < 128) {
                int gi = min(NNODES - 1, max(0, n0 - 2 + tid));
                while (((volatile int*)g_flag)[gi] == 0) __nanosleep(128);
            }
            __threadfence();
            __syncthreads();

            // ---- LN1 + bf16 split -> A tiles ----
            const int c0 = 2 * L, c2 = 64 + 2 * L;
#pragma unroll 4
            for (int t = 0; t < 16; t++) {
                int row = w + 8 * t;
                int gi  = min(NNODES - 1, max(0, n0 - 2 + row));
                const float* p = &g_buf0[((size_t)b * NNODES + gi) * GHD + c0];
                float2 v0 = *(const float2*)p;
                float2 v1 = *(const float2*)(p + 64);
                float s = v0.x + v0.y + v1.x + v1.y;
                float q = v0.x * v0.x + v0.y * v0.y + v1.x * v1.x + v1.y * v1.y;
#pragma unroll
                for (int o = 16; o; o >>= 1) {
                    s += __shfl_xor_sync(0xFFFFFFFFu, s, o);
                    q += __shfl_xor_sync(0xFFFFFFFFu, q, o);
                }
                float mu   = s * (1.0f / GHD);
                float rstd = rsqrtf(fmaxf(q * (1.0f / GHD) - mu * mu, 0.0f) + LN_EPS);
                float f0 = (v0.x - mu) * rstd * sG1[c0] + sB1[c0];
                float f1 = (v0.y - mu) * rstd * sG1[c0 + 1] + sB1[c0 + 1];
                float f2 = (v1.x - mu) * rstd * sG1[c2] + sB1[c2];
                float f3 = (v1.y - mu) * rstd * sG1[c2 + 1] + sB1[c2 + 1];
                u32 h0, l0, h1, l1;
                split2(f0, f1, h0, l0);
                split2(f2, f3, h1, l1);
                *(u32*)(dynsm + G_AHI + row * GSB + L * 4)       = h0;
                *(u32*)(dynsm + G_AHI + row * GSB + 128 + L * 4) = h1;
                *(u32*)(dynsm + G_ALO + row * GSB + L * 4)       = l0;
                *(u32*)(dynsm + G_ALO + row * GSB + 128 + L * 4) = l1;
            }
            __syncthreads();

            // ---- MMA: full N=128, B-image-major pass order ----
            const int mw = w & 3, nh = w >> 2;
            const int R0 = mw * 32;
            const u32 arow = (u32)(L & 15);
            const u32 kcol = (u32)((L >> 4) << 3);
            const float K1 = g_K[0], K2 = g_K[1];

            float acc[2][2][4][4];
#pragma unroll
            for (int ns = 0; ns < 2; ns++)
#pragma unroll
                for (int mt = 0; mt < 2; mt++)
#pragma unroll
                    for (int j = 0; j < 4; j++)
#pragma unroll
                        for (int c = 0; c < 4; c++) acc[ns][mt][j][c] = 0.0f;

            // Phase 1: (Ahi + Alo) * Bhi
#pragma unroll
            for (int ks = 0; ks < 8; ks++) {
                u32 kb = (u32)((ks * 16 + kcol) * 2);
                u32 ah0[4], ah1[4], al0[4], al1[4];
                ldsm4(ah0, sb + G_AHI + (R0 + arow) * GSB + kb);
                ldsm4(ah1, sb + G_AHI + (R0 + 16 + arow) * GSB + kb);
                ldsm4(al0, sb + G_ALO + (R0 + arow) * GSB + kb);
                ldsm4(al1, sb + G_ALO + (R0 + 16 + arow) * GSB + kb);
#pragma unroll
                for (int ns = 0; ns < 2; ns++) {
                    int N0 = nh * 32 + ns * 64;
                    u32 bf[2][4];
#pragma unroll
                    for (int g = 0; g < 2; g++)
                        ldsm4(bf[g], sb + G_BREG + (N0 + g * 16 + arow) * GSB + kb);
#pragma unroll
                    for (int j = 0; j < 4; j++) {
                        u32 b0 = bf[j >> 1][(j & 1)];
                        u32 b1 = bf[j >> 1][(j & 1) + 2];
                        mma16816(acc[ns][0][j], ah0, b0, b1);
                        mma16816(acc[ns][1][j], ah1, b0, b1);
                        mma16816(acc[ns][0][j], al0, b0, b1);
                        mma16816(acc[ns][1][j], al1, b0, b1);
                    }
                }
            }
            __syncthreads();               // Bhi reads done -> restage as Blo
            {
                uint4* dh = (uint4*)(dynsm + G_BREG);
                for (int i = tid; i < 2176; i += 256)
                    dh[i] = ((const uint4*)g_BL)[i];
            }
            __syncthreads();

            // Phase 2: Ahi * Blo
#pragma unroll
            for (int ks = 0; ks < 8; ks++) {
                u32 kb = (u32)((ks * 16 + kcol) * 2);
                u32 ah0[4], ah1[4];
                ldsm4(ah0, sb + G_AHI + (R0 + arow) * GSB + kb);
                ldsm4(ah1, sb + G_AHI + (R0 + 16 + arow) * GSB + kb);
#pragma unroll
                for (int ns = 0; ns < 2; ns++) {
                    int N0 = nh * 32 + ns * 64;
                    u32 bf[2][4];
#pragma unroll
                    for (int g = 0; g < 2; g++)
                        ldsm4(bf[g], sb + G_BREG + (N0 + g * 16 + arow) * GSB + kb);
#pragma unroll
                    for (int j = 0; j < 4; j++) {
                        u32 b0 = bf[j >> 1][(j & 1)];
                        u32 b1 = bf[j >> 1][(j & 1) + 2];
                        mma16816(acc[ns][0][j], ah0, b0, b1);
                        mma16816(acc[ns][1][j], ah1, b0, b1);
                    }
                }
            }
            __syncthreads();               // A reads done -> A region becomes C

            // ---- C frags -> sC (A region, stride 136 floats) ----
            float* sC = (float*)(dynsm + G_AHI);
#pragma unroll
            for (int ns = 0; ns < 2; ns++) {
#pragma unroll
                for (int mt = 0; mt < 2; mt++) {
                    int m = R0 + mt * 16 + (L >> 2);
                    int n = nh * 32 + ns * 64 + (L & 3) * 2;
#pragma unroll
                    for (int j = 0; j < 4; j++) {
                        *(float2*)&sC[m * 136 + n + j * 8] =
                            make_float2(acc[ns][mt][j][0], acc[ns][mt][j][1]);
                        *(float2*)&sC[(m + 8) * 136 + n + j * 8] =
                            make_float2(acc[ns][mt][j][2], acc[ns][mt][j][3]);
                    }
                }
            }
            __syncthreads();

            // ---- single full-width dot pass -> sT, sU ----
#pragma unroll 2
            for (int t = 0; t < 16; t++) {
                int row = w + 8 * t;
                if (row < 1 || row > 126) continue;
                int gi = min(NNODES - 1, max(0, n0 - 2 + row));
                const float* p = &g_buf0[((size_t)b * NNODES + gi) * GHD + c0];
                float2 iv0 = *(const float2*)p;
                float2 iv1 = *(const float2*)(p + 64);
                float2 wp0 = *(const float2*)&sC[(row - 1) * 136 + c0];
                float2 wp1 = *(const float2*)&sC[(row - 1) * 136 + c2];
                float2 wn0 = *(const float2*)&sC[(row + 1) * 136 + c0];
                float2 wn1 = *(const float2*)&sC[(row + 1) * 136 + c2];
                float ap = sAp[row], an = sAn[row];
                float o0 = fmaf(an, wn0.x, fmaf(ap, wp0.x, iv0.x));
                float o1 = fmaf(an, wn0.y, fmaf(ap, wp0.y, iv0.y));
                float o2 = fmaf(an, wn1.x, fmaf(ap, wp1.x, iv1.x));
                float o3 = fmaf(an, wn1.y, fmaf(ap, wp1.y, iv1.y));
                float sv = o0 + o1 + o2 + o3;
                float sq = o0 * o0 + o1 * o1 + o2 * o2 + o3 * o3;
                float st = o0 * sWo[c0] + o1 * sWo[c0 + 1] +
                           o2 * sWo[c2] + o3 * sWo[c2 + 1];
                float sg = o0 * sGw[c0] + o1 * sGw[c0 + 1] +
                           o2 * sGw[c2] + o3 * sGw[c2 + 1];
#pragma unroll
                for (int o = 16; o; o >>= 1) {
                    sv += __shfl_xor_sync(0xFFFFFFFFu, sv, o);
                    sq += __shfl_xor_sync(0xFFFFFFFFu, sq, o);
                    st += __shfl_xor_sync(0xFFFFFFFFu, st, o);
                    sg += __shfl_xor_sync(0xFFFFFFFFu, sg, o);
                }
                if (L == 0) {
                    float mu   = sv * (1.0f / GHD);
                    float rstd = rsqrtf(fmaxf(sq * (1.0f / GHD) - mu * mu, 0.0f) +
                                        LN_EPS);
                    sT[row] = st;
                    sU[row] = rstd * (sg - mu * K1) + K2;
                }
            }
            __syncthreads();

            // ---- final: rows 2..125 -> proj ----
            if (tid < 124) {
                int row = tid + 2;
                int gi  = n0 + tid;
                if (gi < NNODES) {
                    float f = sT[row] + sAp[row] * sU[row - 1] +
                              sAn[row] * sU[row + 1] + bout[0];
                    proj[b * NNODES + gi] = f;
                }
            }
        }
        __syncthreads();                   // smem reuse barrier before next unit
    }
}

// ===========================================================================
extern "C" void kernel_launch(void* const* d_in, const int* in_sizes, int n_in,
                              void* d_out, int out_size) {
    const float* x    = (const float*)d_in[0];
    const float* Ah   = (const float*)d_in[1];
    const float* W1   = (const float*)d_in[2];
    const float* b1   = (const float*)d_in[3];
    const float* W2   = (const float*)d_in[4];
    const float* b2   = (const float*)d_in[5];
    const float* Wg1  = (const float*)d_in[6];
    const float* Wg2  = (const float*)d_in[7];
    const float* g1   = (const float*)d_in[8];
    const float* bb1  = (const float*)d_in[9];
    const float* g2   = (const float*)d_in[10];
    const float* bb2  = (const float*)d_in[11];
    const float* Wout = (const float*)d_in[12];
    const float* bout = (const float*)d_in[13];
    float* out = (float*)d_out;

    cudaFuncSetAttribute(k_mega, cudaFuncAttributeMaxDynamicSharedMemorySize,
                         G_SMEM);

    k_init<<<66, ENC_HID>>>(x, W1, b1, Wg1, Wg2, Wout, g2, bb2);
    k_mega<<<N_PERS, 256, G_SMEM>>>(W2, b2, Ah, g1, bb1, Wout, bout, out);
}

// round 17
// speedup vs baseline: 1.2654x; 1.0109x over previous
#include <cuda_runtime.h>
#include <cuda_bf16.h>

typedef unsigned int       u32;
typedef unsigned long long u64;

#define BSZ      64
#define ENC_IN   64
#define ENC_HID  256
#define NNODES   2048
#define GHD      128
#define JTOT     (NNODES * GHD)      // 262144
#define LN_EPS   1e-5f

#define N_INIT    66
#define N_ENC_BLK NNODES             // enc units (one node each)
#define N_GCN_BLK (17 * BSZ)         // 1088 gcn units
#define U_ENC0    N_INIT
#define U_GCN0    (N_INIT + N_ENC_BLK)          // 2114
#define U_END     (N_INIT + N_ENC_BLK + N_GCN_BLK)  // 3202
#define N_PERS    304                // persistent blocks (152 SMs x 2)

// ---------------- scratch (device globals: allocation-guard safe) ----------
__device__ float g_buf0[(size_t)BSZ * NNODES * GHD];   // enc output
// A (=h1) bf16 hi/lo smem-image, row stride 528B (132 u32), 64 rows
__device__ __align__(16) u32 g_AH[64 * 132];
__device__ __align__(16) u32 g_AL[64 * 132];
// Wg1 transposed [n][k] bf16 hi/lo image, row stride 136 halfs (= 68 u32)
__device__ __align__(16) u32 g_BH[GHD * 68];
__device__ __align__(16) u32 g_BL[GHD * 68];
// layer-2 collapse: w2o = Wg2 @ Wout; gw = g2*w2o; K = {sum gw, sum b2*w2o}
__device__ float g_gw[GHD];
__device__ float g_K[2];
// sync array: [0]=ticket, [1]=init_done, [2]=exit_cnt, [3..3+2048)=node flags
#define SY_TICKET 0
#define SY_INIT   1
#define SY_EXIT   2
#define SY_FLAG   3
__device__ int g_sync[3 + NNODES];

extern __shared__ __align__(1024) char dynsm[];

// ---------------- helpers ---------------------------------------------------
__device__ __forceinline__ u32 smem_u32(const void* p) {
    u32 a;
    asm("{ .reg .u64 t; cvta.to.shared.u64 t, %1; cvt.u32.u64 %0, t; }"
        : "=r"(a) : "l"(p));
    return a;
}
__device__ __forceinline__ void ldsm4(u32* r, u32 a) {
    asm volatile("ldmatrix.sync.aligned.m8n8.x4.shared.b16 {%0,%1,%2,%3}, [%4];"
                 : "=r"(r[0]), "=r"(r[1]), "=r"(r[2]), "=r"(r[3]) : "r"(a));
}
__device__ __forceinline__ void ldsm4t(u32* r, u32 a) {
    asm volatile("ldmatrix.sync.aligned.m8n8.x4.trans.shared.b16 {%0,%1,%2,%3}, [%4];"
                 : "=r"(r[0]), "=r"(r[1]), "=r"(r[2]), "=r"(r[3]) : "r"(a));
}
__device__ __forceinline__ void mma16816(float* c, const u32* a, u32 b0, u32 b1) {
    asm volatile(
        "mma.sync.aligned.m16n8k16.row.col.f32.bf16.bf16.f32 "
        "{%0,%1,%2,%3}, {%4,%5,%6,%7}, {%8,%9}, {%0,%1,%2,%3};"
        : "+f"(c[0]), "+f"(c[1]), "+f"(c[2]), "+f"(c[3])
        : "r"(a[0]), "r"(a[1]), "r"(a[2]), "r"(a[3]), "r"(b0), "r"(b1));
}
__device__ __forceinline__ void split2(float a, float b, u32& hi, u32& lo) {
    __nv_bfloat162 h = __floats2bfloat162_rn(a, b);
    float ha = __bfloat162float(h.x), hb = __bfloat162float(h.y);
    __nv_bfloat162 l = __floats2bfloat162_rn(a - ha, b - hb);
    hi = *reinterpret_cast<u32*>(&h);
    lo = *reinterpret_cast<u32*>(&l);
}

// enc-role smem offsets
#define ESB       528
#define EBB       272
#define E_AHI     0
#define E_ALO     33792
#define E_B0HI    67584
#define E_B0LO    76288
#define E_B1HI    84992
#define E_B1LO    93696
// gcn-role smem offsets
#define GSB       272
#define G_AHI     0
#define G_ALO     34816
#define G_BREG    69632                    // full-N B image (hi, then lo) / C in A region
#define G_SMEM    104448

// ===========================================================================
// K_MEGA — persistent; tickets: [0,66) init units, [66,2114) enc, [2114,3202)
// gcn. Self-cleaning: last exiting block zeroes g_sync for the next replay.
// ===========================================================================
__global__ __launch_bounds__(256, 2) void k_mega(const float* __restrict__ x,
                                                 const float* __restrict__ W1,
                                                 const float* __restrict__ b1,
                                                 const float* __restrict__ Wg1,
                                                 const float* __restrict__ Wg2,
                                                 const float* __restrict__ g2v,
                                                 const float* __restrict__ bb2v,
                                                 const float* __restrict__ W2,
                                                 const float* __restrict__ b2,
                                                 const float* __restrict__ Ah,
                                                 const float* __restrict__ g1,
                                                 const float* __restrict__ bb1,
                                                 const float* __restrict__ Wout,
                                                 const float* __restrict__ bout,
                                                 float* __restrict__ proj) {
    __shared__ float sAp[128], sAn[128];
    __shared__ float sG1[128], sB1[128], sWo[128], sGw[128];
    __shared__ float sT[128], sU[128];
    __shared__ int s_u, s_ready, s_astaged, s_last;

    const int tid = threadIdx.x;
    const int L   = tid & 31;
    const int w   = tid >> 5;
    const u32 sb  = smem_u32(dynsm);

    if (tid == 0) { s_ready = 0; s_astaged = 0; }
    __syncthreads();

    for (;;) {
        if (tid == 0) s_u = atomicAdd(&g_sync[SY_TICKET], 1);
        __syncthreads();
        const int u = s_u;
        if (u >= U_END) break;

        if (u < N_INIT) {
            // ================= init unit =================
            if (u < 64) {
                // h1 row-block for batch u + its bf16 A-image row
                float* sxf = (float*)dynsm;            // 64 floats
                float* shf = (float*)(dynsm + 1024);   // 256 floats
                if (tid < ENC_IN) sxf[tid] = x[u * ENC_IN + tid];
                __syncthreads();
                float acc = b1[tid];
#pragma unroll
                for (int k = 0; k < ENC_IN; k++)
                    acc = fmaf(sxf[k], W1[k * ENC_HID + tid], acc);
                shf[tid] = fmaxf(acc, 0.0f);
                __syncthreads();
                if (tid < 128) {
                    u32 hi, lo;
                    split2(shf[2 * tid], shf[2 * tid + 1], hi, lo);
                    g_AH[u * 132 + tid] = hi;
                    g_AL[u * 132 + tid] = lo;
                }
            } else if (u == 64) {
                if (tid < GHD) {
                    for (int k = 0; k < GHD; k += 2) {
                        u32 hi, lo;
                        split2(Wg1[k * GHD + tid], Wg1[(k + 1) * GHD + tid], hi, lo);
                        g_BH[tid * 68 + (k >> 1)] = hi;
                        g_BL[tid * 68 + (k >> 1)] = lo;
                    }
                }
            } else {
                float* sr1 = (float*)dynsm;            // 128 floats
                float* sr2 = (float*)(dynsm + 1024);   // 128 floats
                if (tid < GHD) {
                    float w2o = 0.0f;
                    for (int d = 0; d < GHD; d++)
                        w2o = fmaf(Wg2[tid * GHD + d], Wout[d], w2o);
                    float gwv = g2v[tid] * w2o;
                    g_gw[tid] = gwv;
                    sr1[tid] = gwv;
                    sr2[tid] = bb2v[tid] * w2o;
                }
                __syncthreads();
                if (tid == 0) {
                    float k1 = 0.0f, k2 = 0.0f;
                    for (int i = 0; i < GHD; i++) { k1 += sr1[i]; k2 += sr2[i]; }
                    g_K[0] = k1;
                    g_K[1] = k2;
                }
            }
            __threadfence();
            __syncthreads();
            if (tid == 0) atomicAdd(&g_sync[SY_INIT], 1);
        } else if (u < U_GCN0) {
            // ================= enc unit =================
            if (!s_astaged) {
                if (!s_ready) {
                    if (tid == 0)
                        while (((volatile int*)g_sync)[SY_INIT] < N_INIT)
                            __nanosleep(64);
                    __syncthreads();
                    if (tid == 0) s_ready = 1;
                }
                // stage A image once per block
                uint4* dh = (uint4*)(dynsm + E_AHI);
                uint4* dl = (uint4*)(dynsm + E_ALO);
                const uint4* shp = (const uint4*)g_AH;
                const uint4* slp = (const uint4*)g_AL;
                for (int i = tid; i < 2112; i += 256) {
                    dh[i] = shp[i];
                    dl[i] = slp[i];
                }
                __syncthreads();
                if (tid == 0) s_astaged = 1;
            }
            const int e  = u - U_ENC0;
            const int j0 = e * 128;

            const int mw = w & 1, nw = w >> 1;
            const int R0 = mw * 32, N0 = nw * 32;
            const u32 arow = (u32)(L & 15);
            const u32 kcol = (u32)((L >> 4) << 3);
            const u32 brow = (u32)((L & 7) + ((L >> 3) & 1) * 8);
            const u32 bcol = (u32)((L >> 4) << 3);

            float acc[2][4][4];
#pragma unroll
            for (int mt = 0; mt < 2; mt++)
#pragma unroll
                for (int j = 0; j < 4; j++)
#pragma unroll
                    for (int c = 0; c < 4; c++) acc[mt][j][c] = 0.0f;

            float4 pf[4], pf2[4];
#pragma unroll
            for (int t = 0; t < 4; t++) {
                int i = tid + t * 256;
                int row = i >> 5, c4 = i & 31;
                pf[t] = *(const float4*)&W2[(size_t)row * JTOT + j0 + c4 * 4];
            }

            for (int kp = 0; kp < 8; kp++) {
                const u32 bHI = (kp & 1) ? E_B1HI : E_B0HI;
                const u32 bLO = (kp & 1) ? E_B1LO : E_B0LO;
                if (kp < 7) {
#pragma unroll
                    for (int t = 0; t < 4; t++) {
                        int i = tid + t * 256;
                        int row = i >> 5, c4 = i & 31;
                        pf2[t] = *(const float4*)&W2[
                            (size_t)((kp + 1) * 32 + row) * JTOT + j0 + c4 * 4];
                    }
                }
#pragma unroll
                for (int t = 0; t < 4; t++) {
                    int i = tid + t * 256;
                    int row = i >> 5, c4 = i & 31;
                    u32 h0, l0, h1, l1;
                    split2(pf[t].x, pf[t].y, h0, l0);
                    split2(pf[t].z, pf[t].w, h1, l1);
                    *(uint2*)(dynsm + bHI + row * EBB + c4 * 8) = make_uint2(h0, h1);
                    *(uint2*)(dynsm + bLO + row * EBB + c4 * 8) = make_uint2(l0, l1);
                }
                __syncthreads();

#pragma unroll
                for (int ks = 0; ks < 2; ks++) {
                    u32 ka = (u32)((kp * 32 + ks * 16 + kcol) * 2);
                    u32 ah0[4], ah1[4], al0[4], al1[4];
                    ldsm4(ah0, sb + E_AHI + (R0 + arow) * ESB + ka);
                    ldsm4(ah1, sb + E_AHI + (R0 + 16 + arow) * ESB + ka);
                    ldsm4(al0, sb + E_ALO + (R0 + arow) * ESB + ka);
                    ldsm4(al1, sb + E_ALO + (R0 + 16 + arow) * ESB + ka);
                    u32 kb = (u32)((ks * 16 + brow) * EBB);
                    u32 bh[2][4], bl[2][4];
#pragma unroll
                    for (int nt = 0; nt < 2; nt++) {
                        ldsm4t(bh[nt], sb + bHI + kb + (N0 + nt * 16 + bcol) * 2);
                        ldsm4t(bl[nt], sb + bLO + kb + (N0 + nt * 16 + bcol) * 2);
                    }
#pragma unroll
                    for (int j = 0; j < 4; j++) {
                        u32 b0 = bh[j >> 1][(j & 1) * 2];
                        u32 b1 = bh[j >> 1][(j & 1) * 2 + 1];
                        mma16816(acc[0][j], ah0, b0, b1);
                        mma16816(acc[1][j], ah1, b0, b1);
                        mma16816(acc[0][j], al0, b0, b1);
                        mma16816(acc[1][j], al1, b0, b1);
                        u32 c0v = bl[j >> 1][(j & 1) * 2];
                        u32 c1v = bl[j >> 1][(j & 1) * 2 + 1];
                        mma16816(acc[0][j], ah0, c0v, c1v);
                        mma16816(acc[1][j], ah1, c0v, c1v);
                    }
                }
#pragma unroll
                for (int t = 0; t < 4; t++) pf[t] = pf2[t];
            }

            // ---- epilogue ----
            {
                int n = j0 + N0 + (L & 3) * 2;
                float b2v[4][2];
#pragma unroll
                for (int j = 0; j < 4; j++) {
                    b2v[j][0] = __ldg(&b2[n + j * 8]);
                    b2v[j][1] = __ldg(&b2[n + j * 8 + 1]);
                }
#pragma unroll
                for (int mt = 0; mt < 2; mt++) {
                    int m = R0 + mt * 16 + (L >> 2);
#pragma unroll
                    for (int j = 0; j < 4; j++) {
                        *(float2*)&g_buf0[(size_t)m * JTOT + n + j * 8] =
                            make_float2(acc[mt][j][0] + b2v[j][0],
                                        acc[mt][j][1] + b2v[j][1]);
                        *(float2*)&g_buf0[(size_t)(m + 8) * JTOT + n + j * 8] =
                            make_float2(acc[mt][j][2] + b2v[j][0],
                                        acc[mt][j][3] + b2v[j][1]);
                    }
                }
            }

            __threadfence();
            __syncthreads();
            if (tid == 0) ((volatile int*)g_sync)[SY_FLAG + e] = 1;
        } else {
            // ================= gcn unit =================
            if (!s_ready) {
                if (tid == 0) {
                    while (((volatile int*)g_sync)[SY_INIT] < N_INIT)
                        __nanosleep(64);
                    s_ready = 1;
                }
                __syncthreads();
            }
            const int bx = u - U_GCN0;
            const int nt = bx >> 6;            // 0..16
            const int b  = bx & 63;
            const int n0 = nt * 124;           // staged row r <-> gi = n0 - 2 + r

            if (tid < 128) {
                sG1[tid] = g1[tid];
                sB1[tid] = bb1[tid];
                sWo[tid] = Wout[tid];
                sGw[tid] = g_gw[tid];
                int gi = n0 - 2 + tid;
                sAp[tid] = (gi >= 1 && gi < NNODES)
                               ? Ah[(size_t)gi * NNODES + gi - 1] : 0.0f;
                sAn[tid] = (gi >= 0 && gi < NNODES - 1)
                               ? Ah[(size_t)gi * NNODES + gi + 1] : 0.0f;
            }

            // ---- stage Bhi full-N ----
            {
                uint4* dh = (uint4*)(dynsm + G_BREG);
                for (int i = tid; i < 2176; i += 256)
                    dh[i] = ((const uint4*)g_BH)[i];
            }

            // ---- wait for the nodes this tile reads ----
            if (tid < 128) {
                int gi = min(NNODES - 1, max(0, n0 - 2 + tid));
                while (((volatile int*)g_sync)[SY_FLAG + gi] == 0) __nanosleep(128);
            }
            __threadfence();
            __syncthreads();

            // ---- LN1 + bf16 split -> A tiles ----
            const int c0 = 2 * L, c2 = 64 + 2 * L;
#pragma unroll 4
            for (int t = 0; t < 16; t++) {
                int row = w + 8 * t;
                int gi  = min(NNODES - 1, max(0, n0 - 2 + row));
                const float* p = &g_buf0[((size_t)b * NNODES + gi) * GHD + c0];
                float2 v0 = *(const float2*)p;
                float2 v1 = *(const float2*)(p + 64);
                float s = v0.x + v0.y + v1.x + v1.y;
                float q = v0.x * v0.x + v0.y * v0.y + v1.x * v1.x + v1.y * v1.y;
#pragma unroll
                for (int o = 16; o; o >>= 1) {
                    s += __shfl_xor_sync(0xFFFFFFFFu, s, o);
                    q += __shfl_xor_sync(0xFFFFFFFFu, q, o);
                }
                float mu   = s * (1.0f / GHD);
                float rstd = rsqrtf(fmaxf(q * (1.0f / GHD) - mu * mu, 0.0f) + LN_EPS);
                float f0 = (v0.x - mu) * rstd * sG1[c0] + sB1[c0];
                float f1 = (v0.y - mu) * rstd * sG1[c0 + 1] + sB1[c0 + 1];
                float f2 = (v1.x - mu) * rstd * sG1[c2] + sB1[c2];
                float f3 = (v1.y - mu) * rstd * sG1[c2 + 1] + sB1[c2 + 1];
                u32 h0, l0, h1, l1;
                split2(f0, f1, h0, l0);
                split2(f2, f3, h1, l1);
                *(u32*)(dynsm + G_AHI + row * GSB + L * 4)       = h0;
                *(u32*)(dynsm + G_AHI + row * GSB + 128 + L * 4) = h1;
                *(u32*)(dynsm + G_ALO + row * GSB + L * 4)       = l0;
                *(u32*)(dynsm + G_ALO + row * GSB + 128 + L * 4) = l1;
            }
            __syncthreads();

            // ---- MMA: full N=128, B-image-major pass order ----
            const int mw = w & 3, nh = w >> 2;
            const int R0 = mw * 32;
            const u32 arow = (u32)(L & 15);
            const u32 kcol = (u32)((L >> 4) << 3);
            const float K1 = g_K[0], K2 = g_K[1];

            float acc[2][2][4][4];
#pragma unroll
            for (int ns = 0; ns < 2; ns++)
#pragma unroll
                for (int mt = 0; mt < 2; mt++)
#pragma unroll
                    for (int j = 0; j < 4; j++)
#pragma unroll
                        for (int c = 0; c < 4; c++) acc[ns][mt][j][c] = 0.0f;

            // Phase 1: (Ahi + Alo) * Bhi
#pragma unroll
            for (int ks = 0; ks < 8; ks++) {
                u32 kb = (u32)((ks * 16 + kcol) * 2);
                u32 ah0[4], ah1[4], al0[4], al1[4];
                ldsm4(ah0, sb + G_AHI + (R0 + arow) * GSB + kb);
                ldsm4(ah1, sb + G_AHI + (R0 + 16 + arow) * GSB + kb);
                ldsm4(al0, sb + G_ALO + (R0 + arow) * GSB + kb);
                ldsm4(al1, sb + G_ALO + (R0 + 16 + arow) * GSB + kb);
#pragma unroll
                for (int ns = 0; ns < 2; ns++) {
                    int N0 = nh * 32 + ns * 64;
                    u32 bf[2][4];
#pragma unroll
                    for (int g = 0; g < 2; g++)
                        ldsm4(bf[g], sb + G_BREG + (N0 + g * 16 + arow) * GSB + kb);
#pragma unroll
                    for (int j = 0; j < 4; j++) {
                        u32 b0 = bf[j >> 1][(j & 1)];
                        u32 b1 = bf[j >> 1][(j & 1) + 2];
                        mma16816(acc[ns][0][j], ah0, b0, b1);
                        mma16816(acc[ns][1][j], ah1, b0, b1);
                        mma16816(acc[ns][0][j], al0, b0, b1);
                        mma16816(acc[ns][1][j], al1, b0, b1);
                    }
                }
            }
            __syncthreads();               // Bhi reads done -> restage as Blo
            {
                uint4* dh = (uint4*)(dynsm + G_BREG);
                for (int i = tid; i < 2176; i += 256)
                    dh[i] = ((const uint4*)g_BL)[i];
            }
            __syncthreads();

            // Phase 2: Ahi * Blo
#pragma unroll
            for (int ks = 0; ks < 8; ks++) {
                u32 kb = (u32)((ks * 16 + kcol) * 2);
                u32 ah0[4], ah1[4];
                ldsm4(ah0, sb + G_AHI + (R0 + arow) * GSB + kb);
                ldsm4(ah1, sb + G_AHI + (R0 + 16 + arow) * GSB + kb);
#pragma unroll
                for (int ns = 0; ns < 2; ns++) {
                    int N0 = nh * 32 + ns * 64;
                    u32 bf[2][4];
#pragma unroll
                    for (int g = 0; g < 2; g++)
                        ldsm4(bf[g], sb + G_BREG + (N0 + g * 16 + arow) * GSB + kb);
#pragma unroll
                    for (int j = 0; j < 4; j++) {
                        u32 b0 = bf[j >> 1][(j & 1)];
                        u32 b1 = bf[j >> 1][(j & 1) + 2];
                        mma16816(acc[ns][0][j], ah0, b0, b1);
                        mma16816(acc[ns][1][j], ah1, b0, b1);
                    }
                }
            }
            __syncthreads();               // A reads done -> A region becomes C

            // ---- C frags -> sC (A region, stride 136 floats) ----
            float* sC = (float*)(dynsm + G_AHI);
#pragma unroll
            for (int ns = 0; ns < 2; ns++) {
#pragma unroll
                for (int mt = 0; mt < 2; mt++) {
                    int m = R0 + mt * 16 + (L >> 2);
                    int n = nh * 32 + ns * 64 + (L & 3) * 2;
#pragma unroll
                    for (int j = 0; j < 4; j++) {
                        *(float2*)&sC[m * 136 + n + j * 8] =
                            make_float2(acc[ns][mt][j][0], acc[ns][mt][j][1]);
                        *(float2*)&sC[(m + 8) * 136 + n + j * 8] =
                            make_float2(acc[ns][mt][j][2], acc[ns][mt][j][3]);
                    }
                }
            }
            __syncthreads();

            // ---- single full-width dot pass -> sT, sU ----
#pragma unroll 2
            for (int t = 0; t < 16; t++) {
                int row = w + 8 * t;
                if (row < 1 || row > 126) continue;
                int gi = min(NNODES - 1, max(0, n0 - 2 + row));
                const float* p = &g_buf0[((size_t)b * NNODES + gi) * GHD + c0];
                float2 iv0 = *(const float2*)p;
                float2 iv1 = *(const float2*)(p + 64);
                float2 wp0 = *(const float2*)&sC[(row - 1) * 136 + c0];
                float2 wp1 = *(const float2*)&sC[(row - 1) * 136 + c2];
                float2 wn0 = *(const float2*)&sC[(row + 1) * 136 + c0];
                float2 wn1 = *(const float2*)&sC[(row + 1) * 136 + c2];
                float ap = sAp[row], an = sAn[row];
                float o0 = fmaf(an, wn0.x, fmaf(ap, wp0.x, iv0.x));
                float o1 = fmaf(an, wn0.y, fmaf(ap, wp0.y, iv0.y));
                float o2 = fmaf(an, wn1.x, fmaf(ap, wp1.x, iv1.x));
                float o3 = fmaf(an, wn1.y, fmaf(ap, wp1.y, iv1.y));
                float sv = o0 + o1 + o2 + o3;
                float sq = o0 * o0 + o1 * o1 + o2 * o2 + o3 * o3;
                float st = o0 * sWo[c0] + o1 * sWo[c0 + 1] +
                           o2 * sWo[c2] + o3 * sWo[c2 + 1];
                float sg = o0 * sGw[c0] + o1 * sGw[c0 + 1] +
                           o2 * sGw[c2] + o3 * sGw[c2 + 1];
#pragma unroll
                for (int o = 16; o; o >>= 1) {
                    sv += __shfl_xor_sync(0xFFFFFFFFu, sv, o);
                    sq += __shfl_xor_sync(0xFFFFFFFFu, sq, o);
                    st += __shfl_xor_sync(0xFFFFFFFFu, st, o);
                    sg += __shfl_xor_sync(0xFFFFFFFFu, sg, o);
                }
                if (L == 0) {
                    float mu   = sv * (1.0f / GHD);
                    float rstd = rsqrtf(fmaxf(sq * (1.0f / GHD) - mu * mu, 0.0f) +
                                        LN_EPS);
                    sT[row] = st;
                    sU[row] = rstd * (sg - mu * K1) + K2;
                }
            }
            __syncthreads();

            // ---- final: rows 2..125 -> proj ----
            if (tid < 124) {
                int row = tid + 2;
                int gi  = n0 + tid;
                if (gi < NNODES) {
                    float f = sT[row] + sAp[row] * sU[row - 1] +
                              sAn[row] * sU[row + 1] + bout[0];
                    proj[b * NNODES + gi] = f;
                }
            }
        }
        __syncthreads();                   // smem reuse barrier before next unit
    }

    // ---- self-cleaning exit: last block resets g_sync for the next replay ----
    if (tid == 0) {
        int n = atomicAdd(&g_sync[SY_EXIT], 1);
        s_last = (n == N_PERS - 1) ? 1 : 0;
    }
    __syncthreads();
    if (s_last) {
        for (int i = tid; i < NNODES; i += 256) g_sync[SY_FLAG + i] = 0;
        __syncthreads();
        if (tid == 0) {
            g_sync[SY_TICKET] = 0;
            g_sync[SY_INIT]   = 0;
            __threadfence();
            g_sync[SY_EXIT]   = 0;
        }
    }
}

// ===========================================================================
extern "C" void kernel_launch(void* const* d_in, const int* in_sizes, int n_in,
                              void* d_out, int out_size) {
    const float* x    = (const float*)d_in[0];
    const float* Ah   = (const float*)d_in[1];
    const float* W1   = (const float*)d_in[2];
    const float* b1   = (const float*)d_in[3];
    const float* W2   = (const float*)d_in[4];
    const float* b2   = (const float*)d_in[5];
    const float* Wg1  = (const float*)d_in[6];
    const float* Wg2  = (const float*)d_in[7];
    const float* g1   = (const float*)d_in[8];
    const float* bb1  = (const float*)d_in[9];
    const float* g2   = (const float*)d_in[10];
    const float* bb2  = (const float*)d_in[11];
    const float* Wout = (const float*)d_in[12];
    const float* bout = (const float*)d_in[13];
    float* out = (float*)d_out;

    cudaFuncSetAttribute(k_mega, cudaFuncAttributeMaxDynamicSharedMemorySize,
                         G_SMEM);

    k_mega<<<N_PERS, 256, G_SMEM>>>(x, W1, b1, Wg1, Wg2, g2, bb2,
                                    W2, b2, Ah, g1, bb1, Wout, bout, out);
}